// round 14
// baseline (speedup 1.0000x reference)
#include <cuda_runtime.h>
#include <cuda_bf16.h>
#include <cuda_fp16.h>
#include <cstdint>

// Problem constants
#define Bsz   4
#define Ssz   2048
#define HID   2048
#define HEADS 16
#define HDIM  128
#define MBsz  16
#define NCH   128
#define Mrows (Bsz*Ssz)    // 8192
#define Kdim  2048
#define Ndim  2048

// Scratch (device globals: allocation-free rule). 16-bit payload is fp16.
__device__ float g_k[(size_t)Mrows * HID];
__device__ float g_v[(size_t)Mrows * HID];
__device__ float g_o[(size_t)Mrows * HID];
__device__ uint16_t g_ahi[(size_t)Mrows * HID];
__device__ uint16_t g_wk16[(size_t)HID * HID];
__device__ uint16_t g_wv16[(size_t)HID * HID];
__device__ uint16_t g_wo16[(size_t)HID * HID];

// ---------------------------------------------------------------------------
// helpers (baseline PTX only: cp.async / ldmatrix / mma.sync — sm_80 features)
// ---------------------------------------------------------------------------
__device__ __forceinline__ uint32_t smem_u32(const void* p) {
    uint32_t a;
    asm("{ .reg .u64 t; cvta.to.shared.u64 t, %1; cvt.u32.u64 %0, t; }"
        : "=r"(a) : "l"(p));
    return a;
}

#define SWZ(x) ((x) ^ (((x) >> 3) & 0x70))

__device__ __forceinline__ void cp16(uint32_t dst, const void* src) {
    asm volatile("cp.async.cg.shared.global [%0], [%1], 16;\n"
                 :: "r"(dst), "l"(src) : "memory");
}
__device__ __forceinline__ void cp_commit() {
    asm volatile("cp.async.commit_group;\n" ::: "memory");
}
template <int N> __device__ __forceinline__ void cp_wait() {
    asm volatile("cp.async.wait_group %0;\n" :: "n"(N) : "memory");
}

__device__ __forceinline__ void ldsm4(uint32_t r[4], uint32_t a) {
    asm volatile("ldmatrix.sync.aligned.m8n8.x4.shared.b16 {%0,%1,%2,%3}, [%4];"
                 : "=r"(r[0]), "=r"(r[1]), "=r"(r[2]), "=r"(r[3]) : "r"(a));
}
__device__ __forceinline__ void ldsm2(uint32_t& r0, uint32_t& r1, uint32_t a) {
    asm volatile("ldmatrix.sync.aligned.m8n8.x2.shared.b16 {%0,%1}, [%2];"
                 : "=r"(r0), "=r"(r1) : "r"(a));
}

// fp16 mma
__device__ __forceinline__ void mma16816h(float c[4], const uint32_t a[4],
                                          const uint32_t b0, const uint32_t b1) {
    asm volatile(
        "mma.sync.aligned.m16n8k16.row.col.f32.f16.f16.f32 "
        "{%0,%1,%2,%3}, {%4,%5,%6,%7}, {%8,%9}, {%0,%1,%2,%3};"
        : "+f"(c[0]), "+f"(c[1]), "+f"(c[2]), "+f"(c[3])
        : "r"(a[0]), "r"(a[1]), "r"(a[2]), "r"(a[3]), "r"(b0), "r"(b1));
}

__device__ __forceinline__ void hsplit(float x, uint16_t& h, uint16_t& l) {
    __half hb = __float2half_rn(x);
    __half lb = __float2half_rn(x - __half2float(hb));
    h = *(uint16_t*)&hb;
    l = *(uint16_t*)&lb;
}
__device__ __forceinline__ uint16_t f2h(float x) {
    __half hb = __float2half_rn(x);
    return *(uint16_t*)&hb;
}

// ---------------------------------------------------------------------------
// single consolidated converter: x, Wk, Wv, Wo -> fp16 in one launch
// ---------------------------------------------------------------------------
#define CVT_XBLK 16384
#define CVT_WBLK 4096
#define CVT_BLKS (CVT_XBLK + 3 * CVT_WBLK)

__global__ __launch_bounds__(256)
void cvt_all_kernel(const float* __restrict__ x,
                    const float* __restrict__ Wk,
                    const float* __restrict__ Wv,
                    const float* __restrict__ Wo,
                    uint16_t* __restrict__ ax,
                    uint16_t* __restrict__ wk,
                    uint16_t* __restrict__ wv,
                    uint16_t* __restrict__ wo)
{
    int bid = blockIdx.x;
    const float* s;
    uint16_t* d;
    if (bid < CVT_XBLK)                      { s = x;  d = ax; }
    else if (bid < CVT_XBLK + CVT_WBLK)      { s = Wk; d = wk; bid -= CVT_XBLK; }
    else if (bid < CVT_XBLK + 2 * CVT_WBLK)  { s = Wv; d = wv; bid -= CVT_XBLK + CVT_WBLK; }
    else                                     { s = Wo; d = wo; bid -= CVT_XBLK + 2 * CVT_WBLK; }

    size_t i = (size_t)bid * 256 + threadIdx.x;
    float4 v = ((const float4*)s)[i];
    uint16_t h[4];
    h[0] = f2h(v.x); h[1] = f2h(v.y); h[2] = f2h(v.z); h[3] = f2h(v.w);
    *(uint64_t*)(d + 4 * i) = *(uint64_t*)h;
}

// ---------------------------------------------------------------------------
// fp16 single-product GEMM core (R12-proven, occ 2)
// ---------------------------------------------------------------------------
#define TILE_B   16384
#define H2_STAGE (2 * TILE_B)
#define H2_SMEM  (1024 + 3 * H2_STAGE)
#define KTILES   (Kdim / 64)

__device__ __forceinline__ void gemm_h1_body(
    const uint16_t* __restrict__ Ahi,
    const uint16_t* __restrict__ Bh,
    float* __restrict__ C,
    const float* __restrict__ Res,
    uint8_t* smraw)
{
    const uint32_t s0 = (smem_u32(smraw) + 1023u) & ~1023u;

    const int tid  = threadIdx.x;
    const int wid  = tid >> 5;
    const int lane = tid & 31;
    const int wm   = wid & 1;
    const int wn   = wid >> 1;
    const int m0 = blockIdx.y * 128;
    const int n0 = blockIdx.x * 128;

    uint32_t aBase[4];
    {
        int amat = lane >> 3, al = lane & 7;
        int rofs = ((amat & 1) << 3) + al;
        uint32_t akb = (uint32_t)((amat >> 1) << 4);
#pragma unroll
        for (int mf = 0; mf < 4; ++mf) {
            uint32_t r = (uint32_t)(wm * 64 + mf * 16 + rofs) * 128u;
            aBase[mf] = SWZ(r) ^ akb;
        }
    }
    uint32_t bBase[2];
    {
        int bmat = lane >> 3, bl = lane & 7;
        int rofs = ((bmat >> 1) << 3) + bl;
        uint32_t bkb = (uint32_t)((bmat & 1) << 4);
#pragma unroll
        for (int nfp = 0; nfp < 2; ++nfp) {
            uint32_t r = (uint32_t)(wn * 32 + nfp * 16 + rofs) * 128u;
            bBase[nfp] = SWZ(r) ^ bkb;
        }
    }

    auto load_stage = [&](int kt) {
        uint32_t sb = s0 + (uint32_t)(kt % 3) * H2_STAGE;
        const size_t kof = (size_t)kt * 64;
#pragma unroll
        for (int j = 0; j < 4; ++j) {
            int q = j * 256 + tid;
            int row = q >> 3, ch = q & 7;
            uint32_t so = SWZ((uint32_t)(row * 128 + ch * 16));
            size_t ga = (size_t)(m0 + row) * Kdim + kof + (size_t)ch * 8;
            size_t gb = (size_t)(n0 + row) * Kdim + kof + (size_t)ch * 8;
            cp16(sb + so,          Ahi + ga);
            cp16(sb + TILE_B + so, Bh + gb);
        }
        cp_commit();
    };

    float acc[4][4][4];
#pragma unroll
    for (int i = 0; i < 4; ++i)
#pragma unroll
        for (int j = 0; j < 4; ++j)
#pragma unroll
            for (int r = 0; r < 4; ++r) acc[i][j][r] = 0.f;

    load_stage(0);
    load_stage(1);

    for (int it = 0; it < KTILES; ++it) {
        cp_wait<1>();
        __syncthreads();
        if (it + 2 < KTILES) load_stage(it + 2);

        const uint32_t sb = s0 + (uint32_t)(it % 3) * H2_STAGE;
#pragma unroll
        for (int kk = 0; kk < 4; ++kk) {
            const uint32_t kx = (uint32_t)(kk * 32);
            uint32_t ah[4][4];
#pragma unroll
            for (int mf = 0; mf < 4; ++mf)
                ldsm4(ah[mf], sb + (aBase[mf] ^ kx));
            uint32_t bh[4][2];
#pragma unroll
            for (int nfp = 0; nfp < 2; ++nfp) {
                uint32_t t[4];
                ldsm4(t, sb + TILE_B + (bBase[nfp] ^ kx));
                bh[2 * nfp][0] = t[0]; bh[2 * nfp][1] = t[1];
                bh[2 * nfp + 1][0] = t[2]; bh[2 * nfp + 1][1] = t[3];
            }
#pragma unroll
            for (int mf = 0; mf < 4; ++mf)
#pragma unroll
                for (int nf = 0; nf < 4; ++nf)
                    mma16816h(acc[mf][nf], ah[mf], bh[nf][0], bh[nf][1]);
        }
    }

    const int cm = (lane >> 2);
    const int cn = (lane & 3) * 2;
#pragma unroll
    for (int mf = 0; mf < 4; ++mf) {
        const int row = m0 + wm * 64 + mf * 16 + cm;
#pragma unroll
        for (int nf = 0; nf < 4; ++nf) {
            const int col = n0 + wn * 32 + nf * 8 + cn;
            float2 v0 = make_float2(acc[mf][nf][0], acc[mf][nf][1]);
            float2 v1 = make_float2(acc[mf][nf][2], acc[mf][nf][3]);
            if (Res) {
                float2 r0 = *(const float2*)(Res + (size_t)row * Ndim + col);
                float2 r1 = *(const float2*)(Res + (size_t)(row + 8) * Ndim + col);
                v0.x += r0.x; v0.y += r0.y;
                v1.x += r1.x; v1.y += r1.y;
            }
            *(float2*)(C + (size_t)row * Ndim + col)       = v0;
            *(float2*)(C + (size_t)(row + 8) * Ndim + col) = v1;
        }
    }
}

__global__ __launch_bounds__(256, 2)
void gemm_kv_kernel(const uint16_t* __restrict__ Ahi,
                    const uint16_t* __restrict__ Bk,
                    const uint16_t* __restrict__ Bv,
                    float* __restrict__ Ck,
                    float* __restrict__ Cv)
{
    extern __shared__ uint8_t smraw[];
    if (blockIdx.z == 0) gemm_h1_body(Ahi, Bk, Ck, nullptr, smraw);
    else                 gemm_h1_body(Ahi, Bv, Cv, nullptr, smraw);
}

__global__ __launch_bounds__(256, 2)
void gemm_h1_kernel(const uint16_t* __restrict__ Ahi,
                    const uint16_t* __restrict__ Bh,
                    float* __restrict__ C,
                    const float* __restrict__ Res)
{
    extern __shared__ uint8_t smraw[];
    gemm_h1_body(Ahi, Bh, C, Res, smraw);
}

// ---------------------------------------------------------------------------
// RoPE on g_k
// ---------------------------------------------------------------------------
__global__ void rope_kernel(float* __restrict__ k)
{
    const int gid = blockIdx.x * blockDim.x + threadIdx.x;
    const int total = Bsz * Ssz * HEADS * (HDIM / 2);
    if (gid >= total) return;
    const int i   = gid & 63;
    const int h   = (gid >> 6) & (HEADS - 1);
    const int row = gid >> 10;
    const int s   = row & (Ssz - 1);

    const float c = 0.20762050593046013f;   // log2(10000)/64
    const float inv = exp2f(-c * (float)i);
    const float ang = (float)s * inv;
    float sn = sinf(ang), cs = cosf(ang);

    float* p = k + (size_t)row * HID + h * HDIM;
    const float k1 = p[i];
    const float k2 = p[i + 64];
    p[i]      = k1 * cs - k2 * sn;
    p[i + 64] = k2 * cs + k1 * sn;
}

// ---------------------------------------------------------------------------
// Tensor-core TTT scan — e-QUARTER split for occupancy.
// Grid (64 bh, 4 e-quarters), 128 threads (4 warps), ~2 CTAs/SM.
// Per CTA: W [128d x 32e] in fp32 accumulators. Warp w: W d-range
// [32w,32w+32) x e32; pred/out e-slice [8w,8w+8) via ldmatrix.x2 B-frags.
// K (A side) fp16 hi+lo; W / E' (B side) rounded once to fp16.
// ---------------------------------------------------------------------------
#define Q_RAWK   0            // [2][16][128] f32 = 16384
#define Q_RAWV   16384        // [2][16][32]  f32 = 4096
#define Q_KHI    20480        // [2 buf][2 half][2048B] = 8192
#define Q_KLO    28672        // 8192
#define Q_KTHI   36864        // [128][48B] = 6144
#define Q_KTLO   43008        // 6144
#define Q_ETHI   49152        // [32][48B] = 1536
#define Q_WTHI   50688        // [2 half][32*128B] = 8192
#define SCANQ_SMEM 58880

__global__ __launch_bounds__(128, 2)
void ttt_scan_mma(const float* __restrict__ gk,
                  const float* __restrict__ gv,
                  const float* __restrict__ W0,
                  float*       __restrict__ go)
{
    extern __shared__ __align__(16) char sm[];
    const uint32_t sb = smem_u32(sm);

    const int tid  = threadIdx.x;
    const int wid  = tid >> 5;
    const int lane = tid & 31;
    const int bh = blockIdx.x;
    const int eh = blockIdx.y;           // 0..3
    const int b  = bh >> 4, h = bh & 15;
    const int e0 = eh * 32;

    const int mat = lane >> 3, ml = lane & 7;
    const int arow = ((mat & 1) << 3) + ml;          // A-operand (x4)
    const uint32_t akb = (uint32_t)((mat >> 1) << 4);
    const int brow = ((mat >> 1) << 3) + ml;         // B-operand (x4)
    const uint32_t bkb = (uint32_t)((mat & 1) << 4);

    const uint32_t aBaseK = SWZ((uint32_t)(arow * 128)) ^ akb;
    // B-operand x2 pattern for WT: lanes 0-7 -> (n, k0), lanes 8-15 -> (n, k8)
    const uint32_t bkb2 = (uint32_t)((mat & 1) << 4);
    const uint32_t bBaseW2 = SWZ((uint32_t)((8 * wid + ml) * 128)) ^ bkb2;

    const int cr = lane >> 2;
    const int cc = (lane & 3) * 2;

    // W fragments: warp w owns d [32w, 32w+32), e [0,32) local
    float W[2][4][4];
    {
        const float* W0p = W0 + (size_t)bh * (HDIM * HDIM);
#pragma unroll
        for (int t2 = 0; t2 < 2; ++t2) {
            int dt = 32 * wid + 16 * t2;
#pragma unroll
            for (int j = 0; j < 4; ++j) {
                int e = e0 + 8 * j + cc;
                W[t2][j][0] = W0p[(size_t)(dt + cr) * 128 + e];
                W[t2][j][1] = W0p[(size_t)(dt + cr) * 128 + e + 1];
                W[t2][j][2] = W0p[(size_t)(dt + cr + 8) * 128 + e];
                W[t2][j][3] = W0p[(size_t)(dt + cr + 8) * 128 + e + 1];
            }
        }
    }

    const float* kbase = gk + (size_t)b * Ssz * HID + h * HDIM;
    const float* vbase = gv + (size_t)b * Ssz * HID + h * HDIM + e0;
    float*       obase = go + (size_t)b * Ssz * HID + h * HDIM + e0;

    auto dumpW = [&]() {
#pragma unroll
        for (int t2 = 0; t2 < 2; ++t2) {
            int dt = 32 * wid + 16 * t2;
#pragma unroll
            for (int j = 0; j < 4; ++j) {
                int e = 8 * j + cc;
#pragma unroll
                for (int q = 0; q < 4; ++q) {
                    int d  = dt + cr + ((q >> 1) << 3);
                    int ee = e + (q & 1);
                    uint32_t half = (uint32_t)(d >> 6);
                    uint32_t a = SWZ((uint32_t)(ee * 128 + (d & 63) * 2));
                    *(uint16_t*)(sm + Q_WTHI + half * 4096 + a) = f2h(W[t2][j][q]);
                }
            }
        }
    };

    auto loadKV = [&](int c) {
        int buf = c & 1;
        const float* ks = kbase + (size_t)(c * 16) * HID;
        const float* vs = vbase + (size_t)(c * 16) * HID;
#pragma unroll
        for (int j = 0; j < 4; ++j) {
            int q = j * 128 + tid;
            int row = q >> 5, ch = q & 31;
            cp16(sb + Q_RAWK + buf * 8192 + (uint32_t)(row * 512 + ch * 16),
                 ks + (size_t)row * HID + ch * 4);
        }
        {
            int row = tid >> 3, ch = tid & 7;
            cp16(sb + Q_RAWV + buf * 2048 + (uint32_t)(row * 128 + ch * 16),
                 vs + (size_t)row * HID + ch * 4);
        }
        cp_commit();
    };

    auto convK = [&](int c) {
        int buf = c & 1;
        const float* rk = (const float*)(sm + Q_RAWK + buf * 8192);
        int m = tid >> 3, c16 = (tid & 7) * 16;
        __align__(16) uint16_t hb[16], lb[16];
#pragma unroll
        for (int i = 0; i < 16; ++i) hsplit(rk[m * 128 + c16 + i], hb[i], lb[i]);
        uint32_t half = (uint32_t)(c16 >= 64);
        uint32_t ccl  = (uint32_t)((c16 & 63) * 2);
        uint32_t a0 = SWZ((uint32_t)(m * 128) + ccl);
        uint32_t a1 = SWZ((uint32_t)(m * 128) + ccl + 16);
        uint32_t kb = (uint32_t)(Q_KHI + buf * 4096 + half * 2048);
        *(uint4*)(sm + kb + a0) = *(uint4*)&hb[0];
        *(uint4*)(sm + kb + a1) = *(uint4*)&hb[8];
        kb = (uint32_t)(Q_KLO + buf * 4096 + half * 2048);
        *(uint4*)(sm + kb + a0) = *(uint4*)&lb[0];
        *(uint4*)(sm + kb + a1) = *(uint4*)&lb[8];
    };

    auto convKT = [&](int c) {
        int buf = c & 1;
        const float* rk = (const float*)(sm + Q_RAWK + buf * 8192);
        int d = tid;
        __align__(16) uint16_t th[16], tl[16];
#pragma unroll
        for (int m = 0; m < 16; ++m) hsplit(rk[m * 128 + d], th[m], tl[m]);
        *(uint4*)(sm + Q_KTHI + d * 48)      = *(uint4*)&th[0];
        *(uint4*)(sm + Q_KTHI + d * 48 + 16) = *(uint4*)&th[8];
        *(uint4*)(sm + Q_KTLO + d * 48)      = *(uint4*)&tl[0];
        *(uint4*)(sm + Q_KTLO + d * 48 + 16) = *(uint4*)&tl[8];
    };

    float P[4];   // pred fragment: m16 x e8 slice [8*wid, 8*wid+8)

    auto predOnly = [&](int buf, float acc[4]) {
#pragma unroll
        for (int q = 0; q < 4; ++q) acc[q] = 0.f;
#pragma unroll
        for (int kk = 0; kk < 8; ++kk) {
            uint32_t half = (uint32_t)(kk >> 2);
            uint32_t kx   = (uint32_t)((kk & 3) * 32);
            uint32_t ah[4], al[4], b0, b1;
            ldsm4(ah, sb + Q_KHI + buf * 4096 + half * 2048 + (aBaseK ^ kx));
            ldsm4(al, sb + Q_KLO + buf * 4096 + half * 2048 + (aBaseK ^ kx));
            ldsm2(b0, b1, sb + Q_WTHI + half * 4096 + (bBaseW2 ^ kx));
            mma16816h(acc, ah, b0, b1);
            mma16816h(acc, al, b0, b1);
        }
    };

    dumpW();
    loadKV(0);
    cp_wait<0>();
    __syncthreads();
    convK(0);
    __syncthreads();
    predOnly(0, P);

    for (int c = 0; c < NCH; ++c) {
        const int buf = c & 1;
        const bool hasNext = (c + 1 < NCH);
        if (hasNext) loadKV(c + 1);

        convKT(c);

        // E' = (V - pred) / 1024, fp16 (hi only — B side)
        {
            const float* rv = (const float*)(sm + Q_RAWV + buf * 2048);
#pragma unroll
            for (int q = 0; q < 4; ++q) {
                int e = 8 * wid + cc + (q & 1);
                int m = cr + ((q >> 1) << 3);
                float ep = (rv[m * 32 + e] - P[q]) * 0.0009765625f;
                *(uint16_t*)(sm + Q_ETHI + e * 48 + m * 2) = f2h(ep);
            }
        }
        __syncthreads();

        // W += K^T @ E'   (A = K^T hi+lo fp16, B = E' fp16)
        {
            uint32_t aH[2][4], aL[2][4];
#pragma unroll
            for (int t2 = 0; t2 < 2; ++t2) {
                uint32_t ra = (uint32_t)((32 * wid + 16 * t2 + arow) * 48) + akb;
                ldsm4(aH[t2], sb + Q_KTHI + ra);
                ldsm4(aL[t2], sb + Q_KTLO + ra);
            }
#pragma unroll
            for (int p = 0; p < 2; ++p) {
                uint32_t rb = (uint32_t)((16 * p + brow) * 48) + bkb;
                uint32_t th[4];
                ldsm4(th, sb + Q_ETHI + rb);
#pragma unroll
                for (int t2 = 0; t2 < 2; ++t2) {
                    mma16816h(W[t2][2 * p],     aH[t2], th[0], th[1]);
                    mma16816h(W[t2][2 * p],     aL[t2], th[0], th[1]);
                    mma16816h(W[t2][2 * p + 1], aH[t2], th[2], th[3]);
                    mma16816h(W[t2][2 * p + 1], aL[t2], th[2], th[3]);
                }
            }
        }

        dumpW();

        if (hasNext) cp_wait<0>();
        __syncthreads();
        if (hasNext) convK(c + 1);
        __syncthreads();

        // fused: out_c = K_c @ W_new (+ pred_{c+1} = K_{c+1} @ W_new)
        {
            float O[4];
#pragma unroll
            for (int q = 0; q < 4; ++q) { O[q] = 0.f; P[q] = 0.f; }
            const int bufn = (c + 1) & 1;
#pragma unroll
            for (int kk = 0; kk < 8; ++kk) {
                uint32_t half = (uint32_t)(kk >> 2);
                uint32_t kx   = (uint32_t)((kk & 3) * 32);
                uint32_t b0, b1;
                ldsm2(b0, b1, sb + Q_WTHI + half * 4096 + (bBaseW2 ^ kx));

                uint32_t ah[4], al[4];
                ldsm4(ah, sb + Q_KHI + buf * 4096 + half * 2048 + (aBaseK ^ kx));
                ldsm4(al, sb + Q_KLO + buf * 4096 + half * 2048 + (aBaseK ^ kx));
                mma16816h(O, ah, b0, b1);
                mma16816h(O, al, b0, b1);
                if (hasNext) {
                    uint32_t nh[4], nl[4];
                    ldsm4(nh, sb + Q_KHI + bufn * 4096 + half * 2048 + (aBaseK ^ kx));
                    ldsm4(nl, sb + Q_KLO + bufn * 4096 + half * 2048 + (aBaseK ^ kx));
                    mma16816h(P, nh, b0, b1);
                    mma16816h(P, nl, b0, b1);
                }
            }
            {
                int e = 8 * wid + cc;
                size_t r0 = (size_t)(c * 16 + cr) * HID + e;
                size_t r1 = (size_t)(c * 16 + cr + 8) * HID + e;
                *(float2*)(obase + r0) = make_float2(O[0], O[1]);
                *(float2*)(obase + r1) = make_float2(O[2], O[3]);
            }
        }
    }
}

// ---------------------------------------------------------------------------
// LayerNorm fused with fp16 round (hi plane only)
// ---------------------------------------------------------------------------
__global__ __launch_bounds__(256)
void ln_cvt_kernel(const float* __restrict__ o,
                   const float* __restrict__ g,
                   const float* __restrict__ beta,
                   uint16_t* __restrict__ hi)
{
    __shared__ float s1[8], s2[8];
    const int row = blockIdx.x;
    const int t   = threadIdx.x;
    const float* p = o + (size_t)row * HID;

    float4 v0 = *(const float4*)(p + t * 8);
    float4 v1 = *(const float4*)(p + t * 8 + 4);
    float s  = v0.x + v0.y + v0.z + v0.w + v1.x + v1.y + v1.z + v1.w;
    float ss = v0.x*v0.x + v0.y*v0.y + v0.z*v0.z + v0.w*v0.w
             + v1.x*v1.x + v1.y*v1.y + v1.z*v1.z + v1.w*v1.w;
#pragma unroll
    for (int off = 16; off > 0; off >>= 1) {
        s  += __shfl_xor_sync(0xffffffffu, s,  off);
        ss += __shfl_xor_sync(0xffffffffu, ss, off);
    }
    const int w = t >> 5;
    if ((t & 31) == 0) { s1[w] = s; s2[w] = ss; }
    __syncthreads();
    float tot = 0.f, tot2 = 0.f;
#pragma unroll
    for (int i = 0; i < 8; ++i) { tot += s1[i]; tot2 += s2[i]; }
    const float mu  = tot * (1.0f / HID);
    const float var = tot2 * (1.0f / HID) - mu * mu;
    const float inv = rsqrtf(var + 1e-5f);

    float4 g0 = *(const float4*)(g + t * 8);
    float4 g1 = *(const float4*)(g + t * 8 + 4);
    float4 b0 = *(const float4*)(beta + t * 8);
    float4 b1 = *(const float4*)(beta + t * 8 + 4);
    float y[8];
    y[0] = (v0.x - mu) * inv * g0.x + b0.x;
    y[1] = (v0.y - mu) * inv * g0.y + b0.y;
    y[2] = (v0.z - mu) * inv * g0.z + b0.z;
    y[3] = (v0.w - mu) * inv * g0.w + b0.w;
    y[4] = (v1.x - mu) * inv * g1.x + b1.x;
    y[5] = (v1.y - mu) * inv * g1.y + b1.y;
    y[6] = (v1.z - mu) * inv * g1.z + b1.z;
    y[7] = (v1.w - mu) * inv * g1.w + b1.w;

    __align__(16) uint16_t hb[8];
#pragma unroll
    for (int i = 0; i < 8; ++i) hb[i] = f2h(y[i]);
    *(uint4*)(hi + (size_t)row * HID + t * 8) = *(uint4*)hb;
}

// ---------------------------------------------------------------------------
// launch
// ---------------------------------------------------------------------------
extern "C" void kernel_launch(void* const* d_in, const int* in_sizes, int n_in,
                              void* d_out, int out_size)
{
    const float* x   = (const float*)d_in[0];
    const float* Wk  = (const float*)d_in[1];
    const float* Wv  = (const float*)d_in[2];
    const float* Wo  = (const float*)d_in[3];
    const float* lng = (const float*)d_in[4];
    const float* lnb = (const float*)d_in[5];
    const float* W0  = (const float*)d_in[6];
    float* out = (float*)d_out;

    float *gk, *gv, *go;
    uint16_t *ahi, *wk16, *wv16, *wo16;
    cudaGetSymbolAddress((void**)&gk, g_k);
    cudaGetSymbolAddress((void**)&gv, g_v);
    cudaGetSymbolAddress((void**)&go, g_o);
    cudaGetSymbolAddress((void**)&ahi, g_ahi);
    cudaGetSymbolAddress((void**)&wk16, g_wk16);
    cudaGetSymbolAddress((void**)&wv16, g_wv16);
    cudaGetSymbolAddress((void**)&wo16, g_wo16);

    cudaFuncSetAttribute(ttt_scan_mma,
                         cudaFuncAttributeMaxDynamicSharedMemorySize, SCANQ_SMEM);
    cudaFuncSetAttribute(gemm_kv_kernel,
                         cudaFuncAttributeMaxDynamicSharedMemorySize, H2_SMEM);
    cudaFuncSetAttribute(gemm_h1_kernel,
                         cudaFuncAttributeMaxDynamicSharedMemorySize, H2_SMEM);

    // 1. all fp32->fp16 conversions in one launch (x, Wk, Wv, Wo)
    cvt_all_kernel<<<CVT_BLKS, 256>>>(x, Wk, Wv, Wo, ahi, wk16, wv16, wo16);

    // 2. k and v GEMMs merged into one launch
    {
        dim3 gg(Ndim / 128, Mrows / 128, 2);
        gemm_kv_kernel<<<gg, 256, H2_SMEM>>>(ahi, wk16, wv16, gk, gv);
    }

    // 3. RoPE on k
    {
        const int total = Bsz * Ssz * HEADS * (HDIM / 2);
        rope_kernel<<<(total + 255) / 256, 256>>>(gk);
    }

    // 4. TTT scan -> o  (e-quarter split, 256 CTAs, ~2/SM)
    {
        dim3 sg(Bsz * HEADS, 4);
        ttt_scan_mma<<<sg, 128, SCANQ_SMEM>>>(gk, gv, W0, go);
    }

    // 5. LayerNorm fused with fp16 round
    ln_cvt_kernel<<<Mrows, 256>>>(go, lng, lnb, ahi);

    // 6. out = x + o_ln @ Wo^T
    {
        dim3 gg(Ndim / 128, Mrows / 128);
        gemm_h1_kernel<<<gg, 256, H2_SMEM>>>(ahi, wo16, out, x);
    }
}

// round 15
// speedup vs baseline: 1.0073x; 1.0073x over previous
#include <cuda_runtime.h>
#include <cuda_bf16.h>
#include <cuda_fp16.h>
#include <cstdint>

// Problem constants
#define Bsz   4
#define Ssz   2048
#define HID   2048
#define HEADS 16
#define HDIM  128
#define MBsz  16
#define NCH   128
#define Mrows (Bsz*Ssz)    // 8192
#define Kdim  2048
#define Ndim  2048

// Scratch (device globals: allocation-free rule). 16-bit payload is fp16.
__device__ float g_k[(size_t)Mrows * HID];
__device__ float g_v[(size_t)Mrows * HID];
__device__ float g_o[(size_t)Mrows * HID];
__device__ uint16_t g_khi[(size_t)Mrows * HID];
__device__ uint16_t g_klo[(size_t)Mrows * HID];
__device__ uint16_t g_ahi[(size_t)Mrows * HID];
__device__ uint16_t g_wk16[(size_t)HID * HID];
__device__ uint16_t g_wv16[(size_t)HID * HID];
__device__ uint16_t g_wo16[(size_t)HID * HID];

// ---------------------------------------------------------------------------
// helpers
// ---------------------------------------------------------------------------
__device__ __forceinline__ uint32_t smem_u32(const void* p) {
    uint32_t a;
    asm("{ .reg .u64 t; cvta.to.shared.u64 t, %1; cvt.u32.u64 %0, t; }"
        : "=r"(a) : "l"(p));
    return a;
}

#define SWZ(x) ((x) ^ (((x) >> 3) & 0x70))

__device__ __forceinline__ void cp16(uint32_t dst, const void* src) {
    asm volatile("cp.async.cg.shared.global [%0], [%1], 16;\n"
                 :: "r"(dst), "l"(src) : "memory");
}
__device__ __forceinline__ void cp_commit() {
    asm volatile("cp.async.commit_group;\n" ::: "memory");
}
template <int N> __device__ __forceinline__ void cp_wait() {
    asm volatile("cp.async.wait_group %0;\n" :: "n"(N) : "memory");
}

__device__ __forceinline__ void ldsm4(uint32_t r[4], uint32_t a) {
    asm volatile("ldmatrix.sync.aligned.m8n8.x4.shared.b16 {%0,%1,%2,%3}, [%4];"
                 : "=r"(r[0]), "=r"(r[1]), "=r"(r[2]), "=r"(r[3]) : "r"(a));
}
__device__ __forceinline__ void ldsm4t(uint32_t r[4], uint32_t a) {
    asm volatile("ldmatrix.sync.aligned.m8n8.x4.trans.shared.b16 {%0,%1,%2,%3}, [%4];"
                 : "=r"(r[0]), "=r"(r[1]), "=r"(r[2]), "=r"(r[3]) : "r"(a));
}
__device__ __forceinline__ void stsm4t(uint32_t a, uint32_t r0, uint32_t r1,
                                       uint32_t r2, uint32_t r3) {
    asm volatile("stmatrix.sync.aligned.m8n8.x4.trans.shared.b16 [%0], {%1,%2,%3,%4};"
                 :: "r"(a), "r"(r0), "r"(r1), "r"(r2), "r"(r3) : "memory");
}

// fp16 mma
__device__ __forceinline__ void mma16816h(float c[4], const uint32_t a[4],
                                          const uint32_t b0, const uint32_t b1) {
    asm volatile(
        "mma.sync.aligned.m16n8k16.row.col.f32.f16.f16.f32 "
        "{%0,%1,%2,%3}, {%4,%5,%6,%7}, {%8,%9}, {%0,%1,%2,%3};"
        : "+f"(c[0]), "+f"(c[1]), "+f"(c[2]), "+f"(c[3])
        : "r"(a[0]), "r"(a[1]), "r"(a[2]), "r"(a[3]), "r"(b0), "r"(b1));
}

__device__ __forceinline__ void hsplit(float x, uint16_t& h, uint16_t& l) {
    __half hb = __float2half_rn(x);
    __half lb = __float2half_rn(x - __half2float(hb));
    h = *(uint16_t*)&hb;
    l = *(uint16_t*)&lb;
}
__device__ __forceinline__ uint16_t f2h(float x) {
    __half hb = __float2half_rn(x);
    return *(uint16_t*)&hb;
}
__device__ __forceinline__ uint32_t packh2(float a, float b) {
    return (uint32_t)f2h(a) | ((uint32_t)f2h(b) << 16);
}

// ---------------------------------------------------------------------------
// consolidated converter: x, Wk, Wv, Wo -> fp16
// ---------------------------------------------------------------------------
#define CVT_XBLK 16384
#define CVT_WBLK 4096
#define CVT_BLKS (CVT_XBLK + 3 * CVT_WBLK)

__global__ __launch_bounds__(256)
void cvt_all_kernel(const float* __restrict__ x,
                    const float* __restrict__ Wk,
                    const float* __restrict__ Wv,
                    const float* __restrict__ Wo,
                    uint16_t* __restrict__ ax,
                    uint16_t* __restrict__ wk,
                    uint16_t* __restrict__ wv,
                    uint16_t* __restrict__ wo)
{
    int bid = blockIdx.x;
    const float* s;
    uint16_t* d;
    if (bid < CVT_XBLK)                      { s = x;  d = ax; }
    else if (bid < CVT_XBLK + CVT_WBLK)      { s = Wk; d = wk; bid -= CVT_XBLK; }
    else if (bid < CVT_XBLK + 2 * CVT_WBLK)  { s = Wv; d = wv; bid -= CVT_XBLK + CVT_WBLK; }
    else                                     { s = Wo; d = wo; bid -= CVT_XBLK + 2 * CVT_WBLK; }

    size_t i = (size_t)bid * 256 + threadIdx.x;
    float4 v = ((const float4*)s)[i];
    uint16_t h[4];
    h[0] = f2h(v.x); h[1] = f2h(v.y); h[2] = f2h(v.z); h[3] = f2h(v.w);
    *(uint64_t*)(d + 4 * i) = *(uint64_t*)h;
}

// ---------------------------------------------------------------------------
// fp16 single-product GEMM core (R12-proven, occ 2)
// ---------------------------------------------------------------------------
#define TILE_B   16384
#define H2_STAGE (2 * TILE_B)
#define H2_SMEM  (1024 + 3 * H2_STAGE)
#define KTILES   (Kdim / 64)

__device__ __forceinline__ void gemm_h1_body(
    const uint16_t* __restrict__ Ahi,
    const uint16_t* __restrict__ Bh,
    float* __restrict__ C,
    const float* __restrict__ Res,
    uint8_t* smraw)
{
    const uint32_t s0 = (smem_u32(smraw) + 1023u) & ~1023u;

    const int tid  = threadIdx.x;
    const int wid  = tid >> 5;
    const int lane = tid & 31;
    const int wm   = wid & 1;
    const int wn   = wid >> 1;
    const int m0 = blockIdx.y * 128;
    const int n0 = blockIdx.x * 128;

    uint32_t aBase[4];
    {
        int amat = lane >> 3, al = lane & 7;
        int rofs = ((amat & 1) << 3) + al;
        uint32_t akb = (uint32_t)((amat >> 1) << 4);
#pragma unroll
        for (int mf = 0; mf < 4; ++mf) {
            uint32_t r = (uint32_t)(wm * 64 + mf * 16 + rofs) * 128u;
            aBase[mf] = SWZ(r) ^ akb;
        }
    }
    uint32_t bBase[2];
    {
        int bmat = lane >> 3, bl = lane & 7;
        int rofs = ((bmat >> 1) << 3) + bl;
        uint32_t bkb = (uint32_t)((bmat & 1) << 4);
#pragma unroll
        for (int nfp = 0; nfp < 2; ++nfp) {
            uint32_t r = (uint32_t)(wn * 32 + nfp * 16 + rofs) * 128u;
            bBase[nfp] = SWZ(r) ^ bkb;
        }
    }

    auto load_stage = [&](int kt) {
        uint32_t sb = s0 + (uint32_t)(kt % 3) * H2_STAGE;
        const size_t kof = (size_t)kt * 64;
#pragma unroll
        for (int j = 0; j < 4; ++j) {
            int q = j * 256 + tid;
            int row = q >> 3, ch = q & 7;
            uint32_t so = SWZ((uint32_t)(row * 128 + ch * 16));
            size_t ga = (size_t)(m0 + row) * Kdim + kof + (size_t)ch * 8;
            size_t gb = (size_t)(n0 + row) * Kdim + kof + (size_t)ch * 8;
            cp16(sb + so,          Ahi + ga);
            cp16(sb + TILE_B + so, Bh + gb);
        }
        cp_commit();
    };

    float acc[4][4][4];
#pragma unroll
    for (int i = 0; i < 4; ++i)
#pragma unroll
        for (int j = 0; j < 4; ++j)
#pragma unroll
            for (int r = 0; r < 4; ++r) acc[i][j][r] = 0.f;

    load_stage(0);
    load_stage(1);

    for (int it = 0; it < KTILES; ++it) {
        cp_wait<1>();
        __syncthreads();
        if (it + 2 < KTILES) load_stage(it + 2);

        const uint32_t sb = s0 + (uint32_t)(it % 3) * H2_STAGE;
#pragma unroll
        for (int kk = 0; kk < 4; ++kk) {
            const uint32_t kx = (uint32_t)(kk * 32);
            uint32_t ah[4][4];
#pragma unroll
            for (int mf = 0; mf < 4; ++mf)
                ldsm4(ah[mf], sb + (aBase[mf] ^ kx));
            uint32_t bh[4][2];
#pragma unroll
            for (int nfp = 0; nfp < 2; ++nfp) {
                uint32_t t[4];
                ldsm4(t, sb + TILE_B + (bBase[nfp] ^ kx));
                bh[2 * nfp][0] = t[0]; bh[2 * nfp][1] = t[1];
                bh[2 * nfp + 1][0] = t[2]; bh[2 * nfp + 1][1] = t[3];
            }
#pragma unroll
            for (int mf = 0; mf < 4; ++mf)
#pragma unroll
                for (int nf = 0; nf < 4; ++nf)
                    mma16816h(acc[mf][nf], ah[mf], bh[nf][0], bh[nf][1]);
        }
    }

    const int cm = (lane >> 2);
    const int cn = (lane & 3) * 2;
#pragma unroll
    for (int mf = 0; mf < 4; ++mf) {
        const int row = m0 + wm * 64 + mf * 16 + cm;
#pragma unroll
        for (int nf = 0; nf < 4; ++nf) {
            const int col = n0 + wn * 32 + nf * 8 + cn;
            float2 v0 = make_float2(acc[mf][nf][0], acc[mf][nf][1]);
            float2 v1 = make_float2(acc[mf][nf][2], acc[mf][nf][3]);
            if (Res) {
                float2 r0 = *(const float2*)(Res + (size_t)row * Ndim + col);
                float2 r1 = *(const float2*)(Res + (size_t)(row + 8) * Ndim + col);
                v0.x += r0.x; v0.y += r0.y;
                v1.x += r1.x; v1.y += r1.y;
            }
            *(float2*)(C + (size_t)row * Ndim + col)       = v0;
            *(float2*)(C + (size_t)(row + 8) * Ndim + col) = v1;
        }
    }
}

__global__ __launch_bounds__(256, 2)
void gemm_kv_kernel(const uint16_t* __restrict__ Ahi,
                    const uint16_t* __restrict__ Bk,
                    const uint16_t* __restrict__ Bv,
                    float* __restrict__ Ck,
                    float* __restrict__ Cv)
{
    extern __shared__ uint8_t smraw[];
    if (blockIdx.z == 0) gemm_h1_body(Ahi, Bk, Ck, nullptr, smraw);
    else                 gemm_h1_body(Ahi, Bv, Cv, nullptr, smraw);
}

__global__ __launch_bounds__(256, 2)
void gemm_h1_kernel(const uint16_t* __restrict__ Ahi,
                    const uint16_t* __restrict__ Bh,
                    float* __restrict__ C,
                    const float* __restrict__ Res)
{
    extern __shared__ uint8_t smraw[];
    gemm_h1_body(Ahi, Bh, C, Res, smraw);
}

// ---------------------------------------------------------------------------
// RoPE fused with fp16 hi/lo split: reads fp32 k, writes khi/klo fp16 planes
// ---------------------------------------------------------------------------
__global__ void rope_cvt_kernel(const float* __restrict__ k,
                                uint16_t* __restrict__ khi,
                                uint16_t* __restrict__ klo)
{
    const int gid = blockIdx.x * blockDim.x + threadIdx.x;
    const int total = Bsz * Ssz * HEADS * (HDIM / 2);
    if (gid >= total) return;
    const int i   = gid & 63;
    const int h   = (gid >> 6) & (HEADS - 1);
    const int row = gid >> 10;
    const int s   = row & (Ssz - 1);

    const float c = 0.20762050593046013f;   // log2(10000)/64
    const float inv = exp2f(-c * (float)i);
    const float ang = (float)s * inv;
    float sn = sinf(ang), cs = cosf(ang);

    const float* p = k + (size_t)row * HID + h * HDIM;
    const float k1 = p[i];
    const float k2 = p[i + 64];
    float o1 = k1 * cs - k2 * sn;
    float o2 = k2 * cs + k1 * sn;

    uint16_t h1, l1, h2, l2;
    hsplit(o1, h1, l1);
    hsplit(o2, h2, l2);
    size_t base = (size_t)row * HID + h * HDIM;
    khi[base + i]      = h1;
    khi[base + i + 64] = h2;
    klo[base + i]      = l1;
    klo[base + i + 64] = l2;
}

// ---------------------------------------------------------------------------
// Tensor-core TTT scan — e-half split, LDS-minimized:
//  * khi/klo loaded as fp16 straight into swizzled ldsm tiles (no convK)
//  * update A-fragments (K^T) via ldmatrix.x4.trans (no convKT / KT buffers)
//  * W dump via stmatrix.x4.trans (8 ops/warp vs 64 scattered STS)
// Grid (64 bh, 2 e-halves), 128 threads (4 warps).
// ---------------------------------------------------------------------------
#define S_RAWV 0        // [2][16][64] f32 = 8192
#define S_KHI  8192     // [2 buf][2 half][2048B] = 8192
#define S_KLO  16384    // 8192
#define S_ETHI 24576    // [64][48B] = 3072
#define S_WTHI 27648    // [2 half][8192B] = 16384
#define SCAN3_SMEM 44032

__global__ __launch_bounds__(128, 1)
void ttt_scan_mma(const uint16_t* __restrict__ gkhi,
                  const uint16_t* __restrict__ gklo,
                  const float* __restrict__ gv,
                  const float* __restrict__ W0,
                  float*       __restrict__ go)
{
    extern __shared__ __align__(16) char sm[];
    const uint32_t sb = smem_u32(sm);

    const int tid  = threadIdx.x;
    const int wid  = tid >> 5;
    const int lane = tid & 31;
    const int bh = blockIdx.x;
    const int eh = blockIdx.y;
    const int b  = bh >> 4, h = bh & 15;
    const int e0 = eh * 64;

    const int mat = lane >> 3, ml = lane & 7;
    const int arow = ((mat & 1) << 3) + ml;
    const uint32_t akb = (uint32_t)((mat >> 1) << 4);
    const int brow = ((mat >> 1) << 3) + ml;
    const uint32_t bkb = (uint32_t)((mat & 1) << 4);

    const uint32_t aBaseK = SWZ((uint32_t)(arow * 128)) ^ akb;
    const uint32_t bBaseW = SWZ((uint32_t)((16 * wid + brow) * 128)) ^ bkb;

    const int cr = lane >> 2;
    const int cc = (lane & 3) * 2;

    float W[2][8][4];
    {
        const float* W0p = W0 + (size_t)bh * (HDIM * HDIM);
#pragma unroll
        for (int t2 = 0; t2 < 2; ++t2) {
            int dt = 32 * wid + 16 * t2;
#pragma unroll
            for (int j = 0; j < 8; ++j) {
                int e = e0 + 8 * j + cc;
                W[t2][j][0] = W0p[(size_t)(dt + cr) * 128 + e];
                W[t2][j][1] = W0p[(size_t)(dt + cr) * 128 + e + 1];
                W[t2][j][2] = W0p[(size_t)(dt + cr + 8) * 128 + e];
                W[t2][j][3] = W0p[(size_t)(dt + cr + 8) * 128 + e + 1];
            }
        }
    }

    const uint16_t* khbase = gkhi + (size_t)b * Ssz * HID + h * HDIM;
    const uint16_t* klbase = gklo + (size_t)b * Ssz * HID + h * HDIM;
    const float*    vbase  = gv   + (size_t)b * Ssz * HID + h * HDIM + e0;
    float*          obase  = go   + (size_t)b * Ssz * HID + h * HDIM + e0;

    // dumpW via stmatrix.trans: 8 x4-ops per warp
    const uint32_t wdump = S_WTHI + (uint32_t)(wid >> 1) * 8192;
    const uint32_t wcol  = (uint32_t)((wid & 1) * 64 + mat * 16);
    auto dumpW = [&]() {
#pragma unroll
        for (int j = 0; j < 8; ++j) {
            uint32_t wa = wdump + SWZ((uint32_t)((8 * j + ml) * 128) + wcol);
            stsm4t(sb + wa,
                   packh2(W[0][j][0], W[0][j][1]),
                   packh2(W[0][j][2], W[0][j][3]),
                   packh2(W[1][j][0], W[1][j][1]),
                   packh2(W[1][j][2], W[1][j][3]));
        }
    };

    // load khi/klo (fp16, straight into swizzled ldsm tiles) + raw V (fp32)
    auto loadKV = [&](int c) {
        int buf = c & 1;
        const uint16_t* kh = khbase + (size_t)(c * 16) * HID;
        const uint16_t* kl = klbase + (size_t)(c * 16) * HID;
        const float*    vs = vbase  + (size_t)(c * 16) * HID;
#pragma unroll
        for (int j = 0; j < 2; ++j) {
            int q = j * 128 + tid;            // 256 chunks of 16B per plane
            int m = q >> 4, dblk = q & 15;    // d0 = 8*dblk
            uint32_t half = (uint32_t)(dblk >> 3);
            uint32_t so = half * 2048 + SWZ((uint32_t)(m * 128 + (dblk & 7) * 16));
            size_t gofs = (size_t)m * HID + 8 * (size_t)dblk;
            cp16(sb + S_KHI + buf * 4096 + so, kh + gofs);
            cp16(sb + S_KLO + buf * 4096 + so, kl + gofs);
        }
#pragma unroll
        for (int j = 0; j < 2; ++j) {
            int q = j * 128 + tid;            // 256 chunks of 16B
            int m = q >> 4, ch = q & 15;
            cp16(sb + S_RAWV + buf * 4096 + (uint32_t)(m * 256 + ch * 16),
                 vs + (size_t)m * HID + ch * 4);
        }
        cp_commit();
    };

    float P[2][4];

    auto predOnly = [&](int buf, float acc[2][4]) {
#pragma unroll
        for (int f = 0; f < 2; ++f)
#pragma unroll
            for (int q = 0; q < 4; ++q) acc[f][q] = 0.f;
#pragma unroll
        for (int kk = 0; kk < 8; ++kk) {
            uint32_t half = (uint32_t)(kk >> 2);
            uint32_t kx   = (uint32_t)((kk & 3) * 32);
            uint32_t ah[4], al[4], t[4], bh2[2][2];
            ldsm4(ah, sb + S_KHI + buf * 4096 + half * 2048 + (aBaseK ^ kx));
            ldsm4(al, sb + S_KLO + buf * 4096 + half * 2048 + (aBaseK ^ kx));
            ldsm4(t, sb + S_WTHI + half * 8192 + (bBaseW ^ kx));
            bh2[0][0] = t[0]; bh2[0][1] = t[1]; bh2[1][0] = t[2]; bh2[1][1] = t[3];
#pragma unroll
            for (int f = 0; f < 2; ++f) {
                mma16816h(acc[f], ah, bh2[f][0], bh2[f][1]);
                mma16816h(acc[f], al, bh2[f][0], bh2[f][1]);
            }
        }
    };

    dumpW();
    loadKV(0);
    cp_wait<0>();
    __syncthreads();
    predOnly(0, P);

    for (int c = 0; c < NCH; ++c) {
        const int buf = c & 1;
        const bool hasNext = (c + 1 < NCH);

        // E' = (V - pred) / 1024, fp16 (B side)
        {
            const float* rv = (const float*)(sm + S_RAWV + buf * 4096);
#pragma unroll
            for (int f = 0; f < 2; ++f)
#pragma unroll
                for (int q = 0; q < 4; ++q) {
                    int e = 16 * wid + 8 * f + cc + (q & 1);
                    int m = cr + ((q >> 1) << 3);
                    float ep = (rv[m * 64 + e] - P[f][q]) * 0.0009765625f;
                    *(uint16_t*)(sm + S_ETHI + e * 48 + m * 2) = f2h(ep);
                }
        }
        __syncthreads();   // (A) ET visible; WT/bufn readers of prev iter done

        if (hasNext) loadKV(c + 1);   // safe: bufn readers finished before sync A

        // W += K^T @ E'  (A via ldmatrix.trans on Khi/Klo tiles)
        {
            uint32_t aH[2][4], aL[2][4];
#pragma unroll
            for (int t2 = 0; t2 < 2; ++t2) {
                int dt = 32 * wid + 16 * t2;
                uint32_t ra = (uint32_t)((dt >> 6)) * 2048 +
                              (SWZ((uint32_t)(brow * 128 + (dt & 63) * 2)) ^ bkb);
                ldsm4t(aH[t2], sb + S_KHI + buf * 4096 + ra);
                ldsm4t(aL[t2], sb + S_KLO + buf * 4096 + ra);
            }
#pragma unroll
            for (int p = 0; p < 4; ++p) {
                uint32_t rb = (uint32_t)((16 * p + brow) * 48) + bkb;
                uint32_t th[4];
                ldsm4(th, sb + S_ETHI + rb);
#pragma unroll
                for (int t2 = 0; t2 < 2; ++t2) {
                    mma16816h(W[t2][2 * p],     aH[t2], th[0], th[1]);
                    mma16816h(W[t2][2 * p],     aL[t2], th[0], th[1]);
                    mma16816h(W[t2][2 * p + 1], aH[t2], th[2], th[3]);
                    mma16816h(W[t2][2 * p + 1], aL[t2], th[2], th[3]);
                }
            }
        }

        dumpW();

        if (hasNext) cp_wait<0>();
        __syncthreads();   // (B) WT visible; next K/V resident

        // fused: out_c = K_c @ W_new (+ pred_{c+1} = K_{c+1} @ W_new)
        {
            float O[2][4];
#pragma unroll
            for (int f = 0; f < 2; ++f)
#pragma unroll
                for (int q = 0; q < 4; ++q) { O[f][q] = 0.f; P[f][q] = 0.f; }
            const int bufn = (c + 1) & 1;
#pragma unroll
            for (int kk = 0; kk < 8; ++kk) {
                uint32_t half = (uint32_t)(kk >> 2);
                uint32_t kx   = (uint32_t)((kk & 3) * 32);
                uint32_t t[4], bh2[2][2];
                ldsm4(t, sb + S_WTHI + half * 8192 + (bBaseW ^ kx));
                bh2[0][0] = t[0]; bh2[0][1] = t[1]; bh2[1][0] = t[2]; bh2[1][1] = t[3];

                uint32_t ah[4], al[4];
                ldsm4(ah, sb + S_KHI + buf * 4096 + half * 2048 + (aBaseK ^ kx));
                ldsm4(al, sb + S_KLO + buf * 4096 + half * 2048 + (aBaseK ^ kx));
#pragma unroll
                for (int f = 0; f < 2; ++f) {
                    mma16816h(O[f], ah, bh2[f][0], bh2[f][1]);
                    mma16816h(O[f], al, bh2[f][0], bh2[f][1]);
                }
                if (hasNext) {
                    uint32_t nh[4], nl[4];
                    ldsm4(nh, sb + S_KHI + bufn * 4096 + half * 2048 + (aBaseK ^ kx));
                    ldsm4(nl, sb + S_KLO + bufn * 4096 + half * 2048 + (aBaseK ^ kx));
#pragma unroll
                    for (int f = 0; f < 2; ++f) {
                        mma16816h(P[f], nh, bh2[f][0], bh2[f][1]);
                        mma16816h(P[f], nl, bh2[f][0], bh2[f][1]);
                    }
                }
            }
#pragma unroll
            for (int f = 0; f < 2; ++f) {
                int e = 16 * wid + 8 * f + cc;
                size_t r0 = (size_t)(c * 16 + cr) * HID + e;
                size_t r1 = (size_t)(c * 16 + cr + 8) * HID + e;
                *(float2*)(obase + r0) = make_float2(O[f][0], O[f][1]);
                *(float2*)(obase + r1) = make_float2(O[f][2], O[f][3]);
            }
        }
    }
}

// ---------------------------------------------------------------------------
// LayerNorm fused with fp16 round (hi plane only)
// ---------------------------------------------------------------------------
__global__ __launch_bounds__(256)
void ln_cvt_kernel(const float* __restrict__ o,
                   const float* __restrict__ g,
                   const float* __restrict__ beta,
                   uint16_t* __restrict__ hi)
{
    __shared__ float s1[8], s2[8];
    const int row = blockIdx.x;
    const int t   = threadIdx.x;
    const float* p = o + (size_t)row * HID;

    float4 v0 = *(const float4*)(p + t * 8);
    float4 v1 = *(const float4*)(p + t * 8 + 4);
    float s  = v0.x + v0.y + v0.z + v0.w + v1.x + v1.y + v1.z + v1.w;
    float ss = v0.x*v0.x + v0.y*v0.y + v0.z*v0.z + v0.w*v0.w
             + v1.x*v1.x + v1.y*v1.y + v1.z*v1.z + v1.w*v1.w;
#pragma unroll
    for (int off = 16; off > 0; off >>= 1) {
        s  += __shfl_xor_sync(0xffffffffu, s,  off);
        ss += __shfl_xor_sync(0xffffffffu, ss, off);
    }
    const int w = t >> 5;
    if ((t & 31) == 0) { s1[w] = s; s2[w] = ss; }
    __syncthreads();
    float tot = 0.f, tot2 = 0.f;
#pragma unroll
    for (int i = 0; i < 8; ++i) { tot += s1[i]; tot2 += s2[i]; }
    const float mu  = tot * (1.0f / HID);
    const float var = tot2 * (1.0f / HID) - mu * mu;
    const float inv = rsqrtf(var + 1e-5f);

    float4 g0 = *(const float4*)(g + t * 8);
    float4 g1 = *(const float4*)(g + t * 8 + 4);
    float4 b0 = *(const float4*)(beta + t * 8);
    float4 b1 = *(const float4*)(beta + t * 8 + 4);
    float y[8];
    y[0] = (v0.x - mu) * inv * g0.x + b0.x;
    y[1] = (v0.y - mu) * inv * g0.y + b0.y;
    y[2] = (v0.z - mu) * inv * g0.z + b0.z;
    y[3] = (v0.w - mu) * inv * g0.w + b0.w;
    y[4] = (v1.x - mu) * inv * g1.x + b1.x;
    y[5] = (v1.y - mu) * inv * g1.y + b1.y;
    y[6] = (v1.z - mu) * inv * g1.z + b1.z;
    y[7] = (v1.w - mu) * inv * g1.w + b1.w;

    __align__(16) uint16_t hb[8];
#pragma unroll
    for (int i = 0; i < 8; ++i) hb[i] = f2h(y[i]);
    *(uint4*)(hi + (size_t)row * HID + t * 8) = *(uint4*)hb;
}

// ---------------------------------------------------------------------------
// launch
// ---------------------------------------------------------------------------
extern "C" void kernel_launch(void* const* d_in, const int* in_sizes, int n_in,
                              void* d_out, int out_size)
{
    const float* x   = (const float*)d_in[0];
    const float* Wk  = (const float*)d_in[1];
    const float* Wv  = (const float*)d_in[2];
    const float* Wo  = (const float*)d_in[3];
    const float* lng = (const float*)d_in[4];
    const float* lnb = (const float*)d_in[5];
    const float* W0  = (const float*)d_in[6];
    float* out = (float*)d_out;

    float *gk, *gv, *go;
    uint16_t *khi, *klo, *ahi, *wk16, *wv16, *wo16;
    cudaGetSymbolAddress((void**)&gk, g_k);
    cudaGetSymbolAddress((void**)&gv, g_v);
    cudaGetSymbolAddress((void**)&go, g_o);
    cudaGetSymbolAddress((void**)&khi, g_khi);
    cudaGetSymbolAddress((void**)&klo, g_klo);
    cudaGetSymbolAddress((void**)&ahi, g_ahi);
    cudaGetSymbolAddress((void**)&wk16, g_wk16);
    cudaGetSymbolAddress((void**)&wv16, g_wv16);
    cudaGetSymbolAddress((void**)&wo16, g_wo16);

    cudaFuncSetAttribute(ttt_scan_mma,
                         cudaFuncAttributeMaxDynamicSharedMemorySize, SCAN3_SMEM);
    cudaFuncSetAttribute(gemm_kv_kernel,
                         cudaFuncAttributeMaxDynamicSharedMemorySize, H2_SMEM);
    cudaFuncSetAttribute(gemm_h1_kernel,
                         cudaFuncAttributeMaxDynamicSharedMemorySize, H2_SMEM);

    // 1. all fp32->fp16 conversions in one launch (x, Wk, Wv, Wo)
    cvt_all_kernel<<<CVT_BLKS, 256>>>(x, Wk, Wv, Wo, ahi, wk16, wv16, wo16);

    // 2. k and v GEMMs merged into one launch
    {
        dim3 gg(Ndim / 128, Mrows / 128, 2);
        gemm_kv_kernel<<<gg, 256, H2_SMEM>>>(ahi, wk16, wv16, gk, gv);
    }

    // 3. RoPE fused with k hi/lo fp16 split
    {
        const int total = Bsz * Ssz * HEADS * (HDIM / 2);
        rope_cvt_kernel<<<(total + 255) / 256, 256>>>(gk, khi, klo);
    }

    // 4. TTT scan -> o  (e-half split, LDS-minimized)
    {
        dim3 sg(Bsz * HEADS, 2);
        ttt_scan_mma<<<sg, 128, SCAN3_SMEM>>>(khi, klo, gv, W0, go);
    }

    // 5. LayerNorm fused with fp16 round
    ln_cvt_kernel<<<Mrows, 256>>>(go, lng, lnb, ahi);

    // 6. out = x + o_ln @ Wo^T
    {
        dim3 gg(Ndim / 128, Mrows / 128);
        gemm_h1_kernel<<<gg, 256, H2_SMEM>>>(ahi, wo16, out, x);
    }
}

// round 16
// speedup vs baseline: 1.0494x; 1.0418x over previous
#include <cuda_runtime.h>
#include <cuda_bf16.h>
#include <cuda_fp16.h>
#include <cstdint>

// Problem constants
#define Bsz   4
#define Ssz   2048
#define HID   2048
#define HEADS 16
#define HDIM  128
#define MBsz  16
#define NCH   128
#define Mrows (Bsz*Ssz)    // 8192
#define Kdim  2048
#define Ndim  2048

// Scratch (device globals: allocation-free rule). 16-bit payload is fp16.
__device__ float g_k[(size_t)Mrows * HID];
__device__ float g_v[(size_t)Mrows * HID];
__device__ float g_o[(size_t)Mrows * HID];
__device__ uint16_t g_khi[(size_t)Mrows * HID];
__device__ uint16_t g_klo[(size_t)Mrows * HID];
__device__ uint16_t g_ahi[(size_t)Mrows * HID];
__device__ uint16_t g_wk16[(size_t)HID * HID];
__device__ uint16_t g_wv16[(size_t)HID * HID];
__device__ uint16_t g_wo16[(size_t)HID * HID];

// ---------------------------------------------------------------------------
// helpers
// ---------------------------------------------------------------------------
__device__ __forceinline__ uint32_t smem_u32(const void* p) {
    uint32_t a;
    asm("{ .reg .u64 t; cvta.to.shared.u64 t, %1; cvt.u32.u64 %0, t; }"
        : "=r"(a) : "l"(p));
    return a;
}

#define SWZ(x) ((x) ^ (((x) >> 3) & 0x70))

__device__ __forceinline__ void cp16(uint32_t dst, const void* src) {
    asm volatile("cp.async.cg.shared.global [%0], [%1], 16;\n"
                 :: "r"(dst), "l"(src) : "memory");
}
__device__ __forceinline__ void cp_commit() {
    asm volatile("cp.async.commit_group;\n" ::: "memory");
}
template <int N> __device__ __forceinline__ void cp_wait() {
    asm volatile("cp.async.wait_group %0;\n" :: "n"(N) : "memory");
}

__device__ __forceinline__ void ldsm4(uint32_t r[4], uint32_t a) {
    asm volatile("ldmatrix.sync.aligned.m8n8.x4.shared.b16 {%0,%1,%2,%3}, [%4];"
                 : "=r"(r[0]), "=r"(r[1]), "=r"(r[2]), "=r"(r[3]) : "r"(a));
}
__device__ __forceinline__ void ldsm4t(uint32_t r[4], uint32_t a) {
    asm volatile("ldmatrix.sync.aligned.m8n8.x4.trans.shared.b16 {%0,%1,%2,%3}, [%4];"
                 : "=r"(r[0]), "=r"(r[1]), "=r"(r[2]), "=r"(r[3]) : "r"(a));
}
__device__ __forceinline__ void ldsm2(uint32_t& r0, uint32_t& r1, uint32_t a) {
    asm volatile("ldmatrix.sync.aligned.m8n8.x2.shared.b16 {%0,%1}, [%2];"
                 : "=r"(r0), "=r"(r1) : "r"(a));
}
__device__ __forceinline__ void stsm4t(uint32_t a, uint32_t r0, uint32_t r1,
                                       uint32_t r2, uint32_t r3) {
    asm volatile("stmatrix.sync.aligned.m8n8.x4.trans.shared.b16 [%0], {%1,%2,%3,%4};"
                 :: "r"(a), "r"(r0), "r"(r1), "r"(r2), "r"(r3) : "memory");
}

// fp16 mma
__device__ __forceinline__ void mma16816h(float c[4], const uint32_t a[4],
                                          const uint32_t b0, const uint32_t b1) {
    asm volatile(
        "mma.sync.aligned.m16n8k16.row.col.f32.f16.f16.f32 "
        "{%0,%1,%2,%3}, {%4,%5,%6,%7}, {%8,%9}, {%0,%1,%2,%3};"
        : "+f"(c[0]), "+f"(c[1]), "+f"(c[2]), "+f"(c[3])
        : "r"(a[0]), "r"(a[1]), "r"(a[2]), "r"(a[3]), "r"(b0), "r"(b1));
}

__device__ __forceinline__ void hsplit(float x, uint16_t& h, uint16_t& l) {
    __half hb = __float2half_rn(x);
    __half lb = __float2half_rn(x - __half2float(hb));
    h = *(uint16_t*)&hb;
    l = *(uint16_t*)&lb;
}
__device__ __forceinline__ uint16_t f2h(float x) {
    __half hb = __float2half_rn(x);
    return *(uint16_t*)&hb;
}
__device__ __forceinline__ uint32_t packh2(float a, float b) {
    return (uint32_t)f2h(a) | ((uint32_t)f2h(b) << 16);
}

// ---------------------------------------------------------------------------
// consolidated converter: x, Wk, Wv, Wo -> fp16
// ---------------------------------------------------------------------------
#define CVT_XBLK 16384
#define CVT_WBLK 4096
#define CVT_BLKS (CVT_XBLK + 3 * CVT_WBLK)

__global__ __launch_bounds__(256)
void cvt_all_kernel(const float* __restrict__ x,
                    const float* __restrict__ Wk,
                    const float* __restrict__ Wv,
                    const float* __restrict__ Wo,
                    uint16_t* __restrict__ ax,
                    uint16_t* __restrict__ wk,
                    uint16_t* __restrict__ wv,
                    uint16_t* __restrict__ wo)
{
    int bid = blockIdx.x;
    const float* s;
    uint16_t* d;
    if (bid < CVT_XBLK)                      { s = x;  d = ax; }
    else if (bid < CVT_XBLK + CVT_WBLK)      { s = Wk; d = wk; bid -= CVT_XBLK; }
    else if (bid < CVT_XBLK + 2 * CVT_WBLK)  { s = Wv; d = wv; bid -= CVT_XBLK + CVT_WBLK; }
    else                                     { s = Wo; d = wo; bid -= CVT_XBLK + 2 * CVT_WBLK; }

    size_t i = (size_t)bid * 256 + threadIdx.x;
    float4 v = ((const float4*)s)[i];
    uint16_t h[4];
    h[0] = f2h(v.x); h[1] = f2h(v.y); h[2] = f2h(v.z); h[3] = f2h(v.w);
    *(uint64_t*)(d + 4 * i) = *(uint64_t*)h;
}

// ---------------------------------------------------------------------------
// fp16 single-product GEMM core (R12-proven, occ 2)
// ---------------------------------------------------------------------------
#define TILE_B   16384
#define H2_STAGE (2 * TILE_B)
#define H2_SMEM  (1024 + 3 * H2_STAGE)
#define KTILES   (Kdim / 64)

__device__ __forceinline__ void gemm_h1_body(
    const uint16_t* __restrict__ Ahi,
    const uint16_t* __restrict__ Bh,
    float* __restrict__ C,
    const float* __restrict__ Res,
    uint8_t* smraw)
{
    const uint32_t s0 = (smem_u32(smraw) + 1023u) & ~1023u;

    const int tid  = threadIdx.x;
    const int wid  = tid >> 5;
    const int lane = tid & 31;
    const int wm   = wid & 1;
    const int wn   = wid >> 1;
    const int m0 = blockIdx.y * 128;
    const int n0 = blockIdx.x * 128;

    uint32_t aBase[4];
    {
        int amat = lane >> 3, al = lane & 7;
        int rofs = ((amat & 1) << 3) + al;
        uint32_t akb = (uint32_t)((amat >> 1) << 4);
#pragma unroll
        for (int mf = 0; mf < 4; ++mf) {
            uint32_t r = (uint32_t)(wm * 64 + mf * 16 + rofs) * 128u;
            aBase[mf] = SWZ(r) ^ akb;
        }
    }
    uint32_t bBase[2];
    {
        int bmat = lane >> 3, bl = lane & 7;
        int rofs = ((bmat >> 1) << 3) + bl;
        uint32_t bkb = (uint32_t)((bmat & 1) << 4);
#pragma unroll
        for (int nfp = 0; nfp < 2; ++nfp) {
            uint32_t r = (uint32_t)(wn * 32 + nfp * 16 + rofs) * 128u;
            bBase[nfp] = SWZ(r) ^ bkb;
        }
    }

    auto load_stage = [&](int kt) {
        uint32_t sb = s0 + (uint32_t)(kt % 3) * H2_STAGE;
        const size_t kof = (size_t)kt * 64;
#pragma unroll
        for (int j = 0; j < 4; ++j) {
            int q = j * 256 + tid;
            int row = q >> 3, ch = q & 7;
            uint32_t so = SWZ((uint32_t)(row * 128 + ch * 16));
            size_t ga = (size_t)(m0 + row) * Kdim + kof + (size_t)ch * 8;
            size_t gb = (size_t)(n0 + row) * Kdim + kof + (size_t)ch * 8;
            cp16(sb + so,          Ahi + ga);
            cp16(sb + TILE_B + so, Bh + gb);
        }
        cp_commit();
    };

    float acc[4][4][4];
#pragma unroll
    for (int i = 0; i < 4; ++i)
#pragma unroll
        for (int j = 0; j < 4; ++j)
#pragma unroll
            for (int r = 0; r < 4; ++r) acc[i][j][r] = 0.f;

    load_stage(0);
    load_stage(1);

    for (int it = 0; it < KTILES; ++it) {
        cp_wait<1>();
        __syncthreads();
        if (it + 2 < KTILES) load_stage(it + 2);

        const uint32_t sb = s0 + (uint32_t)(it % 3) * H2_STAGE;
#pragma unroll
        for (int kk = 0; kk < 4; ++kk) {
            const uint32_t kx = (uint32_t)(kk * 32);
            uint32_t ah[4][4];
#pragma unroll
            for (int mf = 0; mf < 4; ++mf)
                ldsm4(ah[mf], sb + (aBase[mf] ^ kx));
            uint32_t bh[4][2];
#pragma unroll
            for (int nfp = 0; nfp < 2; ++nfp) {
                uint32_t t[4];
                ldsm4(t, sb + TILE_B + (bBase[nfp] ^ kx));
                bh[2 * nfp][0] = t[0]; bh[2 * nfp][1] = t[1];
                bh[2 * nfp + 1][0] = t[2]; bh[2 * nfp + 1][1] = t[3];
            }
#pragma unroll
            for (int mf = 0; mf < 4; ++mf)
#pragma unroll
                for (int nf = 0; nf < 4; ++nf)
                    mma16816h(acc[mf][nf], ah[mf], bh[nf][0], bh[nf][1]);
        }
    }

    const int cm = (lane >> 2);
    const int cn = (lane & 3) * 2;
#pragma unroll
    for (int mf = 0; mf < 4; ++mf) {
        const int row = m0 + wm * 64 + mf * 16 + cm;
#pragma unroll
        for (int nf = 0; nf < 4; ++nf) {
            const int col = n0 + wn * 32 + nf * 8 + cn;
            float2 v0 = make_float2(acc[mf][nf][0], acc[mf][nf][1]);
            float2 v1 = make_float2(acc[mf][nf][2], acc[mf][nf][3]);
            if (Res) {
                float2 r0 = *(const float2*)(Res + (size_t)row * Ndim + col);
                float2 r1 = *(const float2*)(Res + (size_t)(row + 8) * Ndim + col);
                v0.x += r0.x; v0.y += r0.y;
                v1.x += r1.x; v1.y += r1.y;
            }
            *(float2*)(C + (size_t)row * Ndim + col)       = v0;
            *(float2*)(C + (size_t)(row + 8) * Ndim + col) = v1;
        }
    }
}

__global__ __launch_bounds__(256, 2)
void gemm_kv_kernel(const uint16_t* __restrict__ Ahi,
                    const uint16_t* __restrict__ Bk,
                    const uint16_t* __restrict__ Bv,
                    float* __restrict__ Ck,
                    float* __restrict__ Cv)
{
    extern __shared__ uint8_t smraw[];
    if (blockIdx.z == 0) gemm_h1_body(Ahi, Bk, Ck, nullptr, smraw);
    else                 gemm_h1_body(Ahi, Bv, Cv, nullptr, smraw);
}

__global__ __launch_bounds__(256, 2)
void gemm_h1_kernel(const uint16_t* __restrict__ Ahi,
                    const uint16_t* __restrict__ Bh,
                    float* __restrict__ C,
                    const float* __restrict__ Res)
{
    extern __shared__ uint8_t smraw[];
    gemm_h1_body(Ahi, Bh, C, Res, smraw);
}

// ---------------------------------------------------------------------------
// RoPE fused with fp16 hi/lo split: reads fp32 k, writes khi/klo fp16 planes
// ---------------------------------------------------------------------------
__global__ void rope_cvt_kernel(const float* __restrict__ k,
                                uint16_t* __restrict__ khi,
                                uint16_t* __restrict__ klo)
{
    const int gid = blockIdx.x * blockDim.x + threadIdx.x;
    const int total = Bsz * Ssz * HEADS * (HDIM / 2);
    if (gid >= total) return;
    const int i   = gid & 63;
    const int h   = (gid >> 6) & (HEADS - 1);
    const int row = gid >> 10;
    const int s   = row & (Ssz - 1);

    const float c = 0.20762050593046013f;   // log2(10000)/64
    const float inv = exp2f(-c * (float)i);
    const float ang = (float)s * inv;
    float sn = sinf(ang), cs = cosf(ang);

    const float* p = k + (size_t)row * HID + h * HDIM;
    const float k1 = p[i];
    const float k2 = p[i + 64];
    float o1 = k1 * cs - k2 * sn;
    float o2 = k2 * cs + k1 * sn;

    uint16_t h1, l1, h2, l2;
    hsplit(o1, h1, l1);
    hsplit(o2, h2, l2);
    size_t base = (size_t)row * HID + h * HDIM;
    khi[base + i]      = h1;
    khi[base + i + 64] = h2;
    klo[base + i]      = l1;
    klo[base + i + 64] = l2;
}

// ---------------------------------------------------------------------------
// Tensor-core TTT scan — e-QUARTER split + LDS-minimized (R14 geometry
// algebra x R15 stmatrix/ldsm-trans algebra, both bit-verified).
// Grid (64 bh, 4 e-quarters), 128 threads, ~2 CTAs/SM.
// Warp w: W d-range [32w,32w+32) x e[0,32) local as W[2][4][4];
// pred/out e-slice [8w,8w+8) via ldsm2 B-frags; update A via ldsm4t on K tiles.
// ---------------------------------------------------------------------------
#define Q_RAWV 0        // [2 buf][16][32] f32 = 4096
#define Q_KHI  4096     // [2 buf][2 half][2048B] = 8192
#define Q_KLO  12288    // 8192
#define Q_ETHI 20480    // [32][48B] = 1536 (+pad)
#define Q_WTHI 22528    // [2 half][32*128B] = 8192
#define SCANQ_SMEM 30720

__global__ __launch_bounds__(128, 2)
void ttt_scan_mma(const uint16_t* __restrict__ gkhi,
                  const uint16_t* __restrict__ gklo,
                  const float* __restrict__ gv,
                  const float* __restrict__ W0,
                  float*       __restrict__ go)
{
    extern __shared__ __align__(16) char sm[];
    const uint32_t sb = smem_u32(sm);

    const int tid  = threadIdx.x;
    const int wid  = tid >> 5;
    const int lane = tid & 31;
    const int bh = blockIdx.x;
    const int eh = blockIdx.y;           // 0..3
    const int b  = bh >> 4, h = bh & 15;
    const int e0 = eh * 32;

    const int mat = lane >> 3, ml = lane & 7;
    const int arow = ((mat & 1) << 3) + ml;
    const uint32_t akb = (uint32_t)((mat >> 1) << 4);
    const int brow = ((mat >> 1) << 3) + ml;
    const uint32_t bkb = (uint32_t)((mat & 1) << 4);

    const uint32_t aBaseK = SWZ((uint32_t)(arow * 128)) ^ akb;
    // ldsm2 B pattern (R14-verified): lanes 0-7 -> (e, k0), lanes 8-15 -> (e, k8)
    const uint32_t bBaseW2 = SWZ((uint32_t)((8 * wid + ml) * 128)) ^
                             (uint32_t)((mat & 1) << 4);

    const int cr = lane >> 2;
    const int cc = (lane & 3) * 2;

    // W fragments: warp w owns d [32w,32w+32), e [0,32) local
    float W[2][4][4];
    {
        const float* W0p = W0 + (size_t)bh * (HDIM * HDIM);
#pragma unroll
        for (int t2 = 0; t2 < 2; ++t2) {
            int dt = 32 * wid + 16 * t2;
#pragma unroll
            for (int j = 0; j < 4; ++j) {
                int e = e0 + 8 * j + cc;
                W[t2][j][0] = W0p[(size_t)(dt + cr) * 128 + e];
                W[t2][j][1] = W0p[(size_t)(dt + cr) * 128 + e + 1];
                W[t2][j][2] = W0p[(size_t)(dt + cr + 8) * 128 + e];
                W[t2][j][3] = W0p[(size_t)(dt + cr + 8) * 128 + e + 1];
            }
        }
    }

    const uint16_t* khbase = gkhi + (size_t)b * Ssz * HID + h * HDIM;
    const uint16_t* klbase = gklo + (size_t)b * Ssz * HID + h * HDIM;
    const float*    vbase  = gv   + (size_t)b * Ssz * HID + h * HDIM + e0;
    float*          obase  = go   + (size_t)b * Ssz * HID + h * HDIM + e0;

    // dumpW via stmatrix.trans: 4 x4-ops per warp (R15-verified algebra, j<4)
    const uint32_t wdump = Q_WTHI + (uint32_t)(wid >> 1) * 4096;
    const uint32_t wcol  = (uint32_t)((wid & 1) * 64 + mat * 16);
    auto dumpW = [&]() {
#pragma unroll
        for (int j = 0; j < 4; ++j) {
            uint32_t wa = wdump + SWZ((uint32_t)((8 * j + ml) * 128) + wcol);
            stsm4t(sb + wa,
                   packh2(W[0][j][0], W[0][j][1]),
                   packh2(W[0][j][2], W[0][j][3]),
                   packh2(W[1][j][0], W[1][j][1]),
                   packh2(W[1][j][2], W[1][j][3]));
        }
    };

    // load khi/klo fp16 tiles (full d=128) + V quarter (fp32)
    auto loadKV = [&](int c) {
        int buf = c & 1;
        const uint16_t* kh = khbase + (size_t)(c * 16) * HID;
        const uint16_t* kl = klbase + (size_t)(c * 16) * HID;
        const float*    vs = vbase  + (size_t)(c * 16) * HID;
#pragma unroll
        for (int j = 0; j < 2; ++j) {
            int q = j * 128 + tid;
            int m = q >> 4, dblk = q & 15;
            uint32_t half = (uint32_t)(dblk >> 3);
            uint32_t so = half * 2048 + SWZ((uint32_t)(m * 128 + (dblk & 7) * 16));
            size_t gofs = (size_t)m * HID + 8 * (size_t)dblk;
            cp16(sb + Q_KHI + buf * 4096 + so, kh + gofs);
            cp16(sb + Q_KLO + buf * 4096 + so, kl + gofs);
        }
        {
            int m = tid >> 3, ch = tid & 7;   // 16 rows x 8 chunks of 16B
            cp16(sb + Q_RAWV + buf * 2048 + (uint32_t)(m * 128 + ch * 16),
                 vs + (size_t)m * HID + ch * 4);
        }
        cp_commit();
    };

    float P[4];   // pred fragment: m16 x e8 slice [8*wid, 8*wid+8)

    auto predOnly = [&](int buf, float acc[4]) {
#pragma unroll
        for (int q = 0; q < 4; ++q) acc[q] = 0.f;
#pragma unroll
        for (int kk = 0; kk < 8; ++kk) {
            uint32_t half = (uint32_t)(kk >> 2);
            uint32_t kx   = (uint32_t)((kk & 3) * 32);
            uint32_t ah[4], al[4], b0, b1;
            ldsm4(ah, sb + Q_KHI + buf * 4096 + half * 2048 + (aBaseK ^ kx));
            ldsm4(al, sb + Q_KLO + buf * 4096 + half * 2048 + (aBaseK ^ kx));
            ldsm2(b0, b1, sb + Q_WTHI + half * 4096 + (bBaseW2 ^ kx));
            mma16816h(acc, ah, b0, b1);
            mma16816h(acc, al, b0, b1);
        }
    };

    dumpW();
    loadKV(0);
    cp_wait<0>();
    __syncthreads();
    predOnly(0, P);

    for (int c = 0; c < NCH; ++c) {
        const int buf = c & 1;
        const bool hasNext = (c + 1 < NCH);

        // E' = (V - pred) / 1024, fp16 (B side)
        {
            const float* rv = (const float*)(sm + Q_RAWV + buf * 2048);
#pragma unroll
            for (int q = 0; q < 4; ++q) {
                int e = 8 * wid + cc + (q & 1);
                int m = cr + ((q >> 1) << 3);
                float ep = (rv[m * 32 + e] - P[q]) * 0.0009765625f;
                *(uint16_t*)(sm + Q_ETHI + e * 48 + m * 2) = f2h(ep);
            }
        }
        __syncthreads();   // (A) ET visible; WT/bufn readers of prev iter done

        if (hasNext) loadKV(c + 1);

        // W += K^T @ E'  (A via ldmatrix.trans on Khi/Klo tiles)
        {
            uint32_t aH[2][4], aL[2][4];
#pragma unroll
            for (int t2 = 0; t2 < 2; ++t2) {
                int dt = 32 * wid + 16 * t2;
                uint32_t ra = (uint32_t)((dt >> 6)) * 2048 +
                              (SWZ((uint32_t)(brow * 128 + (dt & 63) * 2)) ^ bkb);
                ldsm4t(aH[t2], sb + Q_KHI + buf * 4096 + ra);
                ldsm4t(aL[t2], sb + Q_KLO + buf * 4096 + ra);
            }
#pragma unroll
            for (int p = 0; p < 2; ++p) {
                uint32_t rb = (uint32_t)((16 * p + brow) * 48) + bkb;
                uint32_t th[4];
                ldsm4(th, sb + Q_ETHI + rb);
#pragma unroll
                for (int t2 = 0; t2 < 2; ++t2) {
                    mma16816h(W[t2][2 * p],     aH[t2], th[0], th[1]);
                    mma16816h(W[t2][2 * p],     aL[t2], th[0], th[1]);
                    mma16816h(W[t2][2 * p + 1], aH[t2], th[2], th[3]);
                    mma16816h(W[t2][2 * p + 1], aL[t2], th[2], th[3]);
                }
            }
        }

        dumpW();

        if (hasNext) cp_wait<0>();
        __syncthreads();   // (B) WT visible; next K/V resident

        // fused: out_c = K_c @ W_new (+ pred_{c+1} = K_{c+1} @ W_new)
        {
            float O[4];
#pragma unroll
            for (int q = 0; q < 4; ++q) { O[q] = 0.f; P[q] = 0.f; }
            const int bufn = (c + 1) & 1;
#pragma unroll
            for (int kk = 0; kk < 8; ++kk) {
                uint32_t half = (uint32_t)(kk >> 2);
                uint32_t kx   = (uint32_t)((kk & 3) * 32);
                uint32_t b0, b1;
                ldsm2(b0, b1, sb + Q_WTHI + half * 4096 + (bBaseW2 ^ kx));

                uint32_t ah[4], al[4];
                ldsm4(ah, sb + Q_KHI + buf * 4096 + half * 2048 + (aBaseK ^ kx));
                ldsm4(al, sb + Q_KLO + buf * 4096 + half * 2048 + (aBaseK ^ kx));
                mma16816h(O, ah, b0, b1);
                mma16816h(O, al, b0, b1);
                if (hasNext) {
                    uint32_t nh[4], nl[4];
                    ldsm4(nh, sb + Q_KHI + bufn * 4096 + half * 2048 + (aBaseK ^ kx));
                    ldsm4(nl, sb + Q_KLO + bufn * 4096 + half * 2048 + (aBaseK ^ kx));
                    mma16816h(P, nh, b0, b1);
                    mma16816h(P, nl, b0, b1);
                }
            }
            {
                int e = 8 * wid + cc;
                size_t r0 = (size_t)(c * 16 + cr) * HID + e;
                size_t r1 = (size_t)(c * 16 + cr + 8) * HID + e;
                *(float2*)(obase + r0) = make_float2(O[0], O[1]);
                *(float2*)(obase + r1) = make_float2(O[2], O[3]);
            }
        }
    }
}

// ---------------------------------------------------------------------------
// LayerNorm fused with fp16 round (hi plane only)
// ---------------------------------------------------------------------------
__global__ __launch_bounds__(256)
void ln_cvt_kernel(const float* __restrict__ o,
                   const float* __restrict__ g,
                   const float* __restrict__ beta,
                   uint16_t* __restrict__ hi)
{
    __shared__ float s1[8], s2[8];
    const int row = blockIdx.x;
    const int t   = threadIdx.x;
    const float* p = o + (size_t)row * HID;

    float4 v0 = *(const float4*)(p + t * 8);
    float4 v1 = *(const float4*)(p + t * 8 + 4);
    float s  = v0.x + v0.y + v0.z + v0.w + v1.x + v1.y + v1.z + v1.w;
    float ss = v0.x*v0.x + v0.y*v0.y + v0.z*v0.z + v0.w*v0.w
             + v1.x*v1.x + v1.y*v1.y + v1.z*v1.z + v1.w*v1.w;
#pragma unroll
    for (int off = 16; off > 0; off >>= 1) {
        s  += __shfl_xor_sync(0xffffffffu, s,  off);
        ss += __shfl_xor_sync(0xffffffffu, ss, off);
    }
    const int w = t >> 5;
    if ((t & 31) == 0) { s1[w] = s; s2[w] = ss; }
    __syncthreads();
    float tot = 0.f, tot2 = 0.f;
#pragma unroll
    for (int i = 0; i < 8; ++i) { tot += s1[i]; tot2 += s2[i]; }
    const float mu  = tot * (1.0f / HID);
    const float var = tot2 * (1.0f / HID) - mu * mu;
    const float inv = rsqrtf(var + 1e-5f);

    float4 g0 = *(const float4*)(g + t * 8);
    float4 g1 = *(const float4*)(g + t * 8 + 4);
    float4 b0 = *(const float4*)(beta + t * 8);
    float4 b1 = *(const float4*)(beta + t * 8 + 4);
    float y[8];
    y[0] = (v0.x - mu) * inv * g0.x + b0.x;
    y[1] = (v0.y - mu) * inv * g0.y + b0.y;
    y[2] = (v0.z - mu) * inv * g0.z + b0.z;
    y[3] = (v0.w - mu) * inv * g0.w + b0.w;
    y[4] = (v1.x - mu) * inv * g1.x + b1.x;
    y[5] = (v1.y - mu) * inv * g1.y + b1.y;
    y[6] = (v1.z - mu) * inv * g1.z + b1.z;
    y[7] = (v1.w - mu) * inv * g1.w + b1.w;

    __align__(16) uint16_t hb[8];
#pragma unroll
    for (int i = 0; i < 8; ++i) hb[i] = f2h(y[i]);
    *(uint4*)(hi + (size_t)row * HID + t * 8) = *(uint4*)hb;
}

// ---------------------------------------------------------------------------
// launch
// ---------------------------------------------------------------------------
extern "C" void kernel_launch(void* const* d_in, const int* in_sizes, int n_in,
                              void* d_out, int out_size)
{
    const float* x   = (const float*)d_in[0];
    const float* Wk  = (const float*)d_in[1];
    const float* Wv  = (const float*)d_in[2];
    const float* Wo  = (const float*)d_in[3];
    const float* lng = (const float*)d_in[4];
    const float* lnb = (const float*)d_in[5];
    const float* W0  = (const float*)d_in[6];
    float* out = (float*)d_out;

    float *gk, *gv, *go;
    uint16_t *khi, *klo, *ahi, *wk16, *wv16, *wo16;
    cudaGetSymbolAddress((void**)&gk, g_k);
    cudaGetSymbolAddress((void**)&gv, g_v);
    cudaGetSymbolAddress((void**)&go, g_o);
    cudaGetSymbolAddress((void**)&khi, g_khi);
    cudaGetSymbolAddress((void**)&klo, g_klo);
    cudaGetSymbolAddress((void**)&ahi, g_ahi);
    cudaGetSymbolAddress((void**)&wk16, g_wk16);
    cudaGetSymbolAddress((void**)&wv16, g_wv16);
    cudaGetSymbolAddress((void**)&wo16, g_wo16);

    cudaFuncSetAttribute(ttt_scan_mma,
                         cudaFuncAttributeMaxDynamicSharedMemorySize, SCANQ_SMEM);
    cudaFuncSetAttribute(gemm_kv_kernel,
                         cudaFuncAttributeMaxDynamicSharedMemorySize, H2_SMEM);
    cudaFuncSetAttribute(gemm_h1_kernel,
                         cudaFuncAttributeMaxDynamicSharedMemorySize, H2_SMEM);

    // 1. all fp32->fp16 conversions in one launch (x, Wk, Wv, Wo)
    cvt_all_kernel<<<CVT_BLKS, 256>>>(x, Wk, Wv, Wo, ahi, wk16, wv16, wo16);

    // 2. k and v GEMMs merged into one launch
    {
        dim3 gg(Ndim / 128, Mrows / 128, 2);
        gemm_kv_kernel<<<gg, 256, H2_SMEM>>>(ahi, wk16, wv16, gk, gv);
    }

    // 3. RoPE fused with k hi/lo fp16 split
    {
        const int total = Bsz * Ssz * HEADS * (HDIM / 2);
        rope_cvt_kernel<<<(total + 255) / 256, 256>>>(gk, khi, klo);
    }

    // 4. TTT scan -> o  (e-quarter split x LDS-minimized, ~2 CTAs/SM)
    {
        dim3 sg(Bsz * HEADS, 4);
        ttt_scan_mma<<<sg, 128, SCANQ_SMEM>>>(khi, klo, gv, W0, go);
    }

    // 5. LayerNorm fused with fp16 round
    ln_cvt_kernel<<<Mrows, 256>>>(go, lng, lnb, ahi);

    // 6. out = x + o_ln @ Wo^T
    {
        dim3 gg(Ndim / 128, Mrows / 128);
        gemm_h1_kernel<<<gg, 256, H2_SMEM>>>(ahi, wo16, out, x);
    }
}

// round 17
// speedup vs baseline: 1.1003x; 1.0485x over previous
#include <cuda_runtime.h>
#include <cuda_bf16.h>
#include <cuda_fp16.h>
#include <cstdint>

// Problem constants
#define Bsz   4
#define Ssz   2048
#define HID   2048
#define HEADS 16
#define HDIM  128
#define MBsz  16
#define NCH   128
#define Mrows (Bsz*Ssz)    // 8192
#define Kdim  2048
#define Ndim  2048

// Scratch (device globals: allocation-free rule). 16-bit payload is fp16.
__device__ float g_k[(size_t)Mrows * HID];
__device__ float g_v[(size_t)Mrows * HID];
__device__ float g_o[(size_t)Mrows * HID];
__device__ uint16_t g_khi[(size_t)Mrows * HID];
__device__ uint16_t g_klo[(size_t)Mrows * HID];
__device__ uint16_t g_ahi[(size_t)Mrows * HID];
__device__ uint16_t g_wk16[(size_t)HID * HID];
__device__ uint16_t g_wv16[(size_t)HID * HID];
__device__ uint16_t g_wo16[(size_t)HID * HID];

// ---------------------------------------------------------------------------
// helpers
// ---------------------------------------------------------------------------
__device__ __forceinline__ uint32_t smem_u32(const void* p) {
    uint32_t a;
    asm("{ .reg .u64 t; cvta.to.shared.u64 t, %1; cvt.u32.u64 %0, t; }"
        : "=r"(a) : "l"(p));
    return a;
}

#define SWZ(x) ((x) ^ (((x) >> 3) & 0x70))

__device__ __forceinline__ void cp16(uint32_t dst, const void* src) {
    asm volatile("cp.async.cg.shared.global [%0], [%1], 16;\n"
                 :: "r"(dst), "l"(src) : "memory");
}
__device__ __forceinline__ void cp_commit() {
    asm volatile("cp.async.commit_group;\n" ::: "memory");
}
template <int N> __device__ __forceinline__ void cp_wait() {
    asm volatile("cp.async.wait_group %0;\n" :: "n"(N) : "memory");
}

__device__ __forceinline__ void ldsm4(uint32_t r[4], uint32_t a) {
    asm volatile("ldmatrix.sync.aligned.m8n8.x4.shared.b16 {%0,%1,%2,%3}, [%4];"
                 : "=r"(r[0]), "=r"(r[1]), "=r"(r[2]), "=r"(r[3]) : "r"(a));
}
__device__ __forceinline__ void ldsm4t(uint32_t r[4], uint32_t a) {
    asm volatile("ldmatrix.sync.aligned.m8n8.x4.trans.shared.b16 {%0,%1,%2,%3}, [%4];"
                 : "=r"(r[0]), "=r"(r[1]), "=r"(r[2]), "=r"(r[3]) : "r"(a));
}
__device__ __forceinline__ void ldsm2(uint32_t& r0, uint32_t& r1, uint32_t a) {
    asm volatile("ldmatrix.sync.aligned.m8n8.x2.shared.b16 {%0,%1}, [%2];"
                 : "=r"(r0), "=r"(r1) : "r"(a));
}
__device__ __forceinline__ void stsm4t(uint32_t a, uint32_t r0, uint32_t r1,
                                       uint32_t r2, uint32_t r3) {
    asm volatile("stmatrix.sync.aligned.m8n8.x4.trans.shared.b16 [%0], {%1,%2,%3,%4};"
                 :: "r"(a), "r"(r0), "r"(r1), "r"(r2), "r"(r3) : "memory");
}

// fp16 mma
__device__ __forceinline__ void mma16816h(float c[4], const uint32_t a[4],
                                          const uint32_t b0, const uint32_t b1) {
    asm volatile(
        "mma.sync.aligned.m16n8k16.row.col.f32.f16.f16.f32 "
        "{%0,%1,%2,%3}, {%4,%5,%6,%7}, {%8,%9}, {%0,%1,%2,%3};"
        : "+f"(c[0]), "+f"(c[1]), "+f"(c[2]), "+f"(c[3])
        : "r"(a[0]), "r"(a[1]), "r"(a[2]), "r"(a[3]), "r"(b0), "r"(b1));
}

__device__ __forceinline__ void hsplit(float x, uint16_t& h, uint16_t& l) {
    __half hb = __float2half_rn(x);
    __half lb = __float2half_rn(x - __half2float(hb));
    h = *(uint16_t*)&hb;
    l = *(uint16_t*)&lb;
}
__device__ __forceinline__ uint16_t f2h(float x) {
    __half hb = __float2half_rn(x);
    return *(uint16_t*)&hb;
}
__device__ __forceinline__ uint32_t packh2(float a, float b) {
    return (uint32_t)f2h(a) | ((uint32_t)f2h(b) << 16);
}

// ---------------------------------------------------------------------------
// consolidated converter: x, Wk, Wv, Wo -> fp16
// ---------------------------------------------------------------------------
#define CVT_XBLK 16384
#define CVT_WBLK 4096
#define CVT_BLKS (CVT_XBLK + 3 * CVT_WBLK)

__global__ __launch_bounds__(256)
void cvt_all_kernel(const float* __restrict__ x,
                    const float* __restrict__ Wk,
                    const float* __restrict__ Wv,
                    const float* __restrict__ Wo,
                    uint16_t* __restrict__ ax,
                    uint16_t* __restrict__ wk,
                    uint16_t* __restrict__ wv,
                    uint16_t* __restrict__ wo)
{
    int bid = blockIdx.x;
    const float* s;
    uint16_t* d;
    if (bid < CVT_XBLK)                      { s = x;  d = ax; }
    else if (bid < CVT_XBLK + CVT_WBLK)      { s = Wk; d = wk; bid -= CVT_XBLK; }
    else if (bid < CVT_XBLK + 2 * CVT_WBLK)  { s = Wv; d = wv; bid -= CVT_XBLK + CVT_WBLK; }
    else                                     { s = Wo; d = wo; bid -= CVT_XBLK + 2 * CVT_WBLK; }

    size_t i = (size_t)bid * 256 + threadIdx.x;
    float4 v = ((const float4*)s)[i];
    uint16_t h[4];
    h[0] = f2h(v.x); h[1] = f2h(v.y); h[2] = f2h(v.z); h[3] = f2h(v.w);
    *(uint64_t*)(d + 4 * i) = *(uint64_t*)h;
}

// ---------------------------------------------------------------------------
// fp16 single-product GEMM core (R12-proven, occ 2)
// ---------------------------------------------------------------------------
#define TILE_B   16384
#define H2_STAGE (2 * TILE_B)
#define H2_SMEM  (1024 + 3 * H2_STAGE)
#define KTILES   (Kdim / 64)

__device__ __forceinline__ void gemm_h1_body(
    const uint16_t* __restrict__ Ahi,
    const uint16_t* __restrict__ Bh,
    float* __restrict__ C,
    const float* __restrict__ Res,
    uint8_t* smraw)
{
    const uint32_t s0 = (smem_u32(smraw) + 1023u) & ~1023u;

    const int tid  = threadIdx.x;
    const int wid  = tid >> 5;
    const int lane = tid & 31;
    const int wm   = wid & 1;
    const int wn   = wid >> 1;
    const int m0 = blockIdx.y * 128;
    const int n0 = blockIdx.x * 128;

    uint32_t aBase[4];
    {
        int amat = lane >> 3, al = lane & 7;
        int rofs = ((amat & 1) << 3) + al;
        uint32_t akb = (uint32_t)((amat >> 1) << 4);
#pragma unroll
        for (int mf = 0; mf < 4; ++mf) {
            uint32_t r = (uint32_t)(wm * 64 + mf * 16 + rofs) * 128u;
            aBase[mf] = SWZ(r) ^ akb;
        }
    }
    uint32_t bBase[2];
    {
        int bmat = lane >> 3, bl = lane & 7;
        int rofs = ((bmat >> 1) << 3) + bl;
        uint32_t bkb = (uint32_t)((bmat & 1) << 4);
#pragma unroll
        for (int nfp = 0; nfp < 2; ++nfp) {
            uint32_t r = (uint32_t)(wn * 32 + nfp * 16 + rofs) * 128u;
            bBase[nfp] = SWZ(r) ^ bkb;
        }
    }

    auto load_stage = [&](int kt) {
        uint32_t sb = s0 + (uint32_t)(kt % 3) * H2_STAGE;
        const size_t kof = (size_t)kt * 64;
#pragma unroll
        for (int j = 0; j < 4; ++j) {
            int q = j * 256 + tid;
            int row = q >> 3, ch = q & 7;
            uint32_t so = SWZ((uint32_t)(row * 128 + ch * 16));
            size_t ga = (size_t)(m0 + row) * Kdim + kof + (size_t)ch * 8;
            size_t gb = (size_t)(n0 + row) * Kdim + kof + (size_t)ch * 8;
            cp16(sb + so,          Ahi + ga);
            cp16(sb + TILE_B + so, Bh + gb);
        }
        cp_commit();
    };

    float acc[4][4][4];
#pragma unroll
    for (int i = 0; i < 4; ++i)
#pragma unroll
        for (int j = 0; j < 4; ++j)
#pragma unroll
            for (int r = 0; r < 4; ++r) acc[i][j][r] = 0.f;

    load_stage(0);
    load_stage(1);

    for (int it = 0; it < KTILES; ++it) {
        cp_wait<1>();
        __syncthreads();
        if (it + 2 < KTILES) load_stage(it + 2);

        const uint32_t sb = s0 + (uint32_t)(it % 3) * H2_STAGE;
#pragma unroll
        for (int kk = 0; kk < 4; ++kk) {
            const uint32_t kx = (uint32_t)(kk * 32);
            uint32_t ah[4][4];
#pragma unroll
            for (int mf = 0; mf < 4; ++mf)
                ldsm4(ah[mf], sb + (aBase[mf] ^ kx));
            uint32_t bh[4][2];
#pragma unroll
            for (int nfp = 0; nfp < 2; ++nfp) {
                uint32_t t[4];
                ldsm4(t, sb + TILE_B + (bBase[nfp] ^ kx));
                bh[2 * nfp][0] = t[0]; bh[2 * nfp][1] = t[1];
                bh[2 * nfp + 1][0] = t[2]; bh[2 * nfp + 1][1] = t[3];
            }
#pragma unroll
            for (int mf = 0; mf < 4; ++mf)
#pragma unroll
                for (int nf = 0; nf < 4; ++nf)
                    mma16816h(acc[mf][nf], ah[mf], bh[nf][0], bh[nf][1]);
        }
    }

    const int cm = (lane >> 2);
    const int cn = (lane & 3) * 2;
#pragma unroll
    for (int mf = 0; mf < 4; ++mf) {
        const int row = m0 + wm * 64 + mf * 16 + cm;
#pragma unroll
        for (int nf = 0; nf < 4; ++nf) {
            const int col = n0 + wn * 32 + nf * 8 + cn;
            float2 v0 = make_float2(acc[mf][nf][0], acc[mf][nf][1]);
            float2 v1 = make_float2(acc[mf][nf][2], acc[mf][nf][3]);
            if (Res) {
                float2 r0 = *(const float2*)(Res + (size_t)row * Ndim + col);
                float2 r1 = *(const float2*)(Res + (size_t)(row + 8) * Ndim + col);
                v0.x += r0.x; v0.y += r0.y;
                v1.x += r1.x; v1.y += r1.y;
            }
            *(float2*)(C + (size_t)row * Ndim + col)       = v0;
            *(float2*)(C + (size_t)(row + 8) * Ndim + col) = v1;
        }
    }
}

__global__ __launch_bounds__(256, 2)
void gemm_kv_kernel(const uint16_t* __restrict__ Ahi,
                    const uint16_t* __restrict__ Bk,
                    const uint16_t* __restrict__ Bv,
                    float* __restrict__ Ck,
                    float* __restrict__ Cv)
{
    extern __shared__ uint8_t smraw[];
    if (blockIdx.z == 0) gemm_h1_body(Ahi, Bk, Ck, nullptr, smraw);
    else                 gemm_h1_body(Ahi, Bv, Cv, nullptr, smraw);
}

__global__ __launch_bounds__(256, 2)
void gemm_h1_kernel(const uint16_t* __restrict__ Ahi,
                    const uint16_t* __restrict__ Bh,
                    float* __restrict__ C,
                    const float* __restrict__ Res)
{
    extern __shared__ uint8_t smraw[];
    gemm_h1_body(Ahi, Bh, C, Res, smraw);
}

// ---------------------------------------------------------------------------
// RoPE fused with fp16 hi/lo split: reads fp32 k, writes khi/klo fp16 planes
// ---------------------------------------------------------------------------
__global__ void rope_cvt_kernel(const float* __restrict__ k,
                                uint16_t* __restrict__ khi,
                                uint16_t* __restrict__ klo)
{
    const int gid = blockIdx.x * blockDim.x + threadIdx.x;
    const int total = Bsz * Ssz * HEADS * (HDIM / 2);
    if (gid >= total) return;
    const int i   = gid & 63;
    const int h   = (gid >> 6) & (HEADS - 1);
    const int row = gid >> 10;
    const int s   = row & (Ssz - 1);

    const float c = 0.20762050593046013f;   // log2(10000)/64
    const float inv = exp2f(-c * (float)i);
    const float ang = (float)s * inv;
    float sn = sinf(ang), cs = cosf(ang);

    const float* p = k + (size_t)row * HID + h * HDIM;
    const float k1 = p[i];
    const float k2 = p[i + 64];
    float o1 = k1 * cs - k2 * sn;
    float o2 = k2 * cs + k1 * sn;

    uint16_t h1, l1, h2, l2;
    hsplit(o1, h1, l1);
    hsplit(o2, h2, l2);
    size_t base = (size_t)row * HID + h * HDIM;
    khi[base + i]      = h1;
    khi[base + i + 64] = h2;
    klo[base + i]      = l1;
    klo[base + i + 64] = l2;
}

// ---------------------------------------------------------------------------
// Tensor-core TTT scan — e-quarter split + LDS-minimized (R16-proven), with
// Klo dropped from pred/out products (kept in the W update — W stays exact).
// Grid (64 bh, 4 e-quarters), 128 threads, ~2 CTAs/SM.
// ---------------------------------------------------------------------------
#define Q_RAWV 0        // [2 buf][16][32] f32 = 4096
#define Q_KHI  4096     // [2 buf][2 half][2048B] = 8192
#define Q_KLO  12288    // 8192
#define Q_ETHI 20480    // [32][48B] = 1536 (+pad)
#define Q_WTHI 22528    // [2 half][32*128B] = 8192
#define SCANQ_SMEM 30720

__global__ __launch_bounds__(128, 2)
void ttt_scan_mma(const uint16_t* __restrict__ gkhi,
                  const uint16_t* __restrict__ gklo,
                  const float* __restrict__ gv,
                  const float* __restrict__ W0,
                  float*       __restrict__ go)
{
    extern __shared__ __align__(16) char sm[];
    const uint32_t sb = smem_u32(sm);

    const int tid  = threadIdx.x;
    const int wid  = tid >> 5;
    const int lane = tid & 31;
    const int bh = blockIdx.x;
    const int eh = blockIdx.y;           // 0..3
    const int b  = bh >> 4, h = bh & 15;
    const int e0 = eh * 32;

    const int mat = lane >> 3, ml = lane & 7;
    const int arow = ((mat & 1) << 3) + ml;
    const uint32_t akb = (uint32_t)((mat >> 1) << 4);
    const int brow = ((mat >> 1) << 3) + ml;
    const uint32_t bkb = (uint32_t)((mat & 1) << 4);

    const uint32_t aBaseK = SWZ((uint32_t)(arow * 128)) ^ akb;
    const uint32_t bBaseW2 = SWZ((uint32_t)((8 * wid + ml) * 128)) ^
                             (uint32_t)((mat & 1) << 4);

    const int cr = lane >> 2;
    const int cc = (lane & 3) * 2;

    float W[2][4][4];
    {
        const float* W0p = W0 + (size_t)bh * (HDIM * HDIM);
#pragma unroll
        for (int t2 = 0; t2 < 2; ++t2) {
            int dt = 32 * wid + 16 * t2;
#pragma unroll
            for (int j = 0; j < 4; ++j) {
                int e = e0 + 8 * j + cc;
                W[t2][j][0] = W0p[(size_t)(dt + cr) * 128 + e];
                W[t2][j][1] = W0p[(size_t)(dt + cr) * 128 + e + 1];
                W[t2][j][2] = W0p[(size_t)(dt + cr + 8) * 128 + e];
                W[t2][j][3] = W0p[(size_t)(dt + cr + 8) * 128 + e + 1];
            }
        }
    }

    const uint16_t* khbase = gkhi + (size_t)b * Ssz * HID + h * HDIM;
    const uint16_t* klbase = gklo + (size_t)b * Ssz * HID + h * HDIM;
    const float*    vbase  = gv   + (size_t)b * Ssz * HID + h * HDIM + e0;
    float*          obase  = go   + (size_t)b * Ssz * HID + h * HDIM + e0;

    const uint32_t wdump = Q_WTHI + (uint32_t)(wid >> 1) * 4096;
    const uint32_t wcol  = (uint32_t)((wid & 1) * 64 + mat * 16);
    auto dumpW = [&]() {
#pragma unroll
        for (int j = 0; j < 4; ++j) {
            uint32_t wa = wdump + SWZ((uint32_t)((8 * j + ml) * 128) + wcol);
            stsm4t(sb + wa,
                   packh2(W[0][j][0], W[0][j][1]),
                   packh2(W[0][j][2], W[0][j][3]),
                   packh2(W[1][j][0], W[1][j][1]),
                   packh2(W[1][j][2], W[1][j][3]));
        }
    };

    auto loadKV = [&](int c) {
        int buf = c & 1;
        const uint16_t* kh = khbase + (size_t)(c * 16) * HID;
        const uint16_t* kl = klbase + (size_t)(c * 16) * HID;
        const float*    vs = vbase  + (size_t)(c * 16) * HID;
#pragma unroll
        for (int j = 0; j < 2; ++j) {
            int q = j * 128 + tid;
            int m = q >> 4, dblk = q & 15;
            uint32_t half = (uint32_t)(dblk >> 3);
            uint32_t so = half * 2048 + SWZ((uint32_t)(m * 128 + (dblk & 7) * 16));
            size_t gofs = (size_t)m * HID + 8 * (size_t)dblk;
            cp16(sb + Q_KHI + buf * 4096 + so, kh + gofs);
            cp16(sb + Q_KLO + buf * 4096 + so, kl + gofs);
        }
        {
            int m = tid >> 3, ch = tid & 7;
            cp16(sb + Q_RAWV + buf * 2048 + (uint32_t)(m * 128 + ch * 16),
                 vs + (size_t)m * HID + ch * 4);
        }
        cp_commit();
    };

    float P[4];

    auto predOnly = [&](int buf, float acc[4]) {
#pragma unroll
        for (int q = 0; q < 4; ++q) acc[q] = 0.f;
#pragma unroll
        for (int kk = 0; kk < 8; ++kk) {
            uint32_t half = (uint32_t)(kk >> 2);
            uint32_t kx   = (uint32_t)((kk & 3) * 32);
            uint32_t ah[4], b0, b1;
            ldsm4(ah, sb + Q_KHI + buf * 4096 + half * 2048 + (aBaseK ^ kx));
            ldsm2(b0, b1, sb + Q_WTHI + half * 4096 + (bBaseW2 ^ kx));
            mma16816h(acc, ah, b0, b1);
        }
    };

    dumpW();
    loadKV(0);
    cp_wait<0>();
    __syncthreads();
    predOnly(0, P);

    for (int c = 0; c < NCH; ++c) {
        const int buf = c & 1;
        const bool hasNext = (c + 1 < NCH);

        // E' = (V - pred) / 1024, fp16 (B side)
        {
            const float* rv = (const float*)(sm + Q_RAWV + buf * 2048);
#pragma unroll
            for (int q = 0; q < 4; ++q) {
                int e = 8 * wid + cc + (q & 1);
                int m = cr + ((q >> 1) << 3);
                float ep = (rv[m * 32 + e] - P[q]) * 0.0009765625f;
                *(uint16_t*)(sm + Q_ETHI + e * 48 + m * 2) = f2h(ep);
            }
        }
        __syncthreads();   // (A) ET visible; WT/bufn readers of prev iter done

        if (hasNext) loadKV(c + 1);

        // W += K^T @ E'  (keeps hi+lo K — W remains full precision)
        {
            uint32_t aH[2][4], aL[2][4];
#pragma unroll
            for (int t2 = 0; t2 < 2; ++t2) {
                int dt = 32 * wid + 16 * t2;
                uint32_t ra = (uint32_t)((dt >> 6)) * 2048 +
                              (SWZ((uint32_t)(brow * 128 + (dt & 63) * 2)) ^ bkb);
                ldsm4t(aH[t2], sb + Q_KHI + buf * 4096 + ra);
                ldsm4t(aL[t2], sb + Q_KLO + buf * 4096 + ra);
            }
#pragma unroll
            for (int p = 0; p < 2; ++p) {
                uint32_t rb = (uint32_t)((16 * p + brow) * 48) + bkb;
                uint32_t th[4];
                ldsm4(th, sb + Q_ETHI + rb);
#pragma unroll
                for (int t2 = 0; t2 < 2; ++t2) {
                    mma16816h(W[t2][2 * p],     aH[t2], th[0], th[1]);
                    mma16816h(W[t2][2 * p],     aL[t2], th[0], th[1]);
                    mma16816h(W[t2][2 * p + 1], aH[t2], th[2], th[3]);
                    mma16816h(W[t2][2 * p + 1], aL[t2], th[2], th[3]);
                }
            }
        }

        dumpW();

        if (hasNext) cp_wait<0>();
        __syncthreads();   // (B) WT visible; next K/V resident

        // fused: out_c = K_c @ W_new (+ pred_{c+1} = K_{c+1} @ W_new)
        // Khi only — K_lo term dropped here (error model ~2.2e-4, self-
        // correcting for pred via the E' feedback).
        {
            float O[4];
#pragma unroll
            for (int q = 0; q < 4; ++q) { O[q] = 0.f; P[q] = 0.f; }
            const int bufn = (c + 1) & 1;
#pragma unroll
            for (int kk = 0; kk < 8; ++kk) {
                uint32_t half = (uint32_t)(kk >> 2);
                uint32_t kx   = (uint32_t)((kk & 3) * 32);
                uint32_t b0, b1;
                ldsm2(b0, b1, sb + Q_WTHI + half * 4096 + (bBaseW2 ^ kx));

                uint32_t ah[4];
                ldsm4(ah, sb + Q_KHI + buf * 4096 + half * 2048 + (aBaseK ^ kx));
                mma16816h(O, ah, b0, b1);
                if (hasNext) {
                    uint32_t nh[4];
                    ldsm4(nh, sb + Q_KHI + bufn * 4096 + half * 2048 + (aBaseK ^ kx));
                    mma16816h(P, nh, b0, b1);
                }
            }
            {
                int e = 8 * wid + cc;
                size_t r0 = (size_t)(c * 16 + cr) * HID + e;
                size_t r1 = (size_t)(c * 16 + cr + 8) * HID + e;
                *(float2*)(obase + r0) = make_float2(O[0], O[1]);
                *(float2*)(obase + r1) = make_float2(O[2], O[3]);
            }
        }
    }
}

// ---------------------------------------------------------------------------
// LayerNorm fused with fp16 round (hi plane only)
// ---------------------------------------------------------------------------
__global__ __launch_bounds__(256)
void ln_cvt_kernel(const float* __restrict__ o,
                   const float* __restrict__ g,
                   const float* __restrict__ beta,
                   uint16_t* __restrict__ hi)
{
    __shared__ float s1[8], s2[8];
    const int row = blockIdx.x;
    const int t   = threadIdx.x;
    const float* p = o + (size_t)row * HID;

    float4 v0 = *(const float4*)(p + t * 8);
    float4 v1 = *(const float4*)(p + t * 8 + 4);
    float s  = v0.x + v0.y + v0.z + v0.w + v1.x + v1.y + v1.z + v1.w;
    float ss = v0.x*v0.x + v0.y*v0.y + v0.z*v0.z + v0.w*v0.w
             + v1.x*v1.x + v1.y*v1.y + v1.z*v1.z + v1.w*v1.w;
#pragma unroll
    for (int off = 16; off > 0; off >>= 1) {
        s  += __shfl_xor_sync(0xffffffffu, s,  off);
        ss += __shfl_xor_sync(0xffffffffu, ss, off);
    }
    const int w = t >> 5;
    if ((t & 31) == 0) { s1[w] = s; s2[w] = ss; }
    __syncthreads();
    float tot = 0.f, tot2 = 0.f;
#pragma unroll
    for (int i = 0; i < 8; ++i) { tot += s1[i]; tot2 += s2[i]; }
    const float mu  = tot * (1.0f / HID);
    const float var = tot2 * (1.0f / HID) - mu * mu;
    const float inv = rsqrtf(var + 1e-5f);

    float4 g0 = *(const float4*)(g + t * 8);
    float4 g1 = *(const float4*)(g + t * 8 + 4);
    float4 b0 = *(const float4*)(beta + t * 8);
    float4 b1 = *(const float4*)(beta + t * 8 + 4);
    float y[8];
    y[0] = (v0.x - mu) * inv * g0.x + b0.x;
    y[1] = (v0.y - mu) * inv * g0.y + b0.y;
    y[2] = (v0.z - mu) * inv * g0.z + b0.z;
    y[3] = (v0.w - mu) * inv * g0.w + b0.w;
    y[4] = (v1.x - mu) * inv * g1.x + b1.x;
    y[5] = (v1.y - mu) * inv * g1.y + b1.y;
    y[6] = (v1.z - mu) * inv * g1.z + b1.z;
    y[7] = (v1.w - mu) * inv * g1.w + b1.w;

    __align__(16) uint16_t hb[8];
#pragma unroll
    for (int i = 0; i < 8; ++i) hb[i] = f2h(y[i]);
    *(uint4*)(hi + (size_t)row * HID + t * 8) = *(uint4*)hb;
}

// ---------------------------------------------------------------------------
// launch
// ---------------------------------------------------------------------------
extern "C" void kernel_launch(void* const* d_in, const int* in_sizes, int n_in,
                              void* d_out, int out_size)
{
    const float* x   = (const float*)d_in[0];
    const float* Wk  = (const float*)d_in[1];
    const float* Wv  = (const float*)d_in[2];
    const float* Wo  = (const float*)d_in[3];
    const float* lng = (const float*)d_in[4];
    const float* lnb = (const float*)d_in[5];
    const float* W0  = (const float*)d_in[6];
    float* out = (float*)d_out;

    float *gk, *gv, *go;
    uint16_t *khi, *klo, *ahi, *wk16, *wv16, *wo16;
    cudaGetSymbolAddress((void**)&gk, g_k);
    cudaGetSymbolAddress((void**)&gv, g_v);
    cudaGetSymbolAddress((void**)&go, g_o);
    cudaGetSymbolAddress((void**)&khi, g_khi);
    cudaGetSymbolAddress((void**)&klo, g_klo);
    cudaGetSymbolAddress((void**)&ahi, g_ahi);
    cudaGetSymbolAddress((void**)&wk16, g_wk16);
    cudaGetSymbolAddress((void**)&wv16, g_wv16);
    cudaGetSymbolAddress((void**)&wo16, g_wo16);

    cudaFuncSetAttribute(ttt_scan_mma,
                         cudaFuncAttributeMaxDynamicSharedMemorySize, SCANQ_SMEM);
    cudaFuncSetAttribute(gemm_kv_kernel,
                         cudaFuncAttributeMaxDynamicSharedMemorySize, H2_SMEM);
    cudaFuncSetAttribute(gemm_h1_kernel,
                         cudaFuncAttributeMaxDynamicSharedMemorySize, H2_SMEM);

    // 1. all fp32->fp16 conversions in one launch (x, Wk, Wv, Wo)
    cvt_all_kernel<<<CVT_BLKS, 256>>>(x, Wk, Wv, Wo, ahi, wk16, wv16, wo16);

    // 2. k and v GEMMs merged into one launch
    {
        dim3 gg(Ndim / 128, Mrows / 128, 2);
        gemm_kv_kernel<<<gg, 256, H2_SMEM>>>(ahi, wk16, wv16, gk, gv);
    }

    // 3. RoPE fused with k hi/lo fp16 split
    {
        const int total = Bsz * Ssz * HEADS * (HDIM / 2);
        rope_cvt_kernel<<<(total + 255) / 256, 256>>>(gk, khi, klo);
    }

    // 4. TTT scan -> o  (e-quarter split, Khi-only pred/out)
    {
        dim3 sg(Bsz * HEADS, 4);
        ttt_scan_mma<<<sg, 128, SCANQ_SMEM>>>(khi, klo, gv, W0, go);
    }

    // 5. LayerNorm fused with fp16 round
    ln_cvt_kernel<<<Mrows, 256>>>(go, lng, lnb, ahi);

    // 6. out = x + o_ln @ Wo^T
    {
        dim3 gg(Ndim / 128, Mrows / 128);
        gemm_h1_kernel<<<gg, 256, H2_SMEM>>>(ahi, wo16, out, x);
    }
}